// round 10
// baseline (speedup 1.0000x reference)
#include <cuda_runtime.h>
#include <cuda_bf16.h>
#include <stdint.h>
#include <math.h>

#define HID 2048
#define SEQ 2048
#define NHEADS 16
#define HDIM 128
#define GROUPS_PER_W (HID*HID/128)

typedef __nv_bfloat16 bf16;

// ---------------- scratch (static device memory; no allocation) ----------------
__device__ __align__(256) bf16  g_xhi[(size_t)SEQ*HID],  g_xlo[(size_t)SEQ*HID];
__device__ __align__(256) bf16  g_whi[4][(size_t)HID*HID], g_wlo[4][(size_t)HID*HID];
__device__ __align__(256) float g_qf[(size_t)SEQ*HID],  g_kf[(size_t)SEQ*HID];
__device__ __align__(256) bf16  g_qhi[(size_t)SEQ*HID], g_qlo[(size_t)SEQ*HID];
__device__ __align__(256) bf16  g_khi[(size_t)SEQ*HID], g_klo[(size_t)SEQ*HID];
__device__ __align__(256) bf16  g_vthi[(size_t)SEQ*HID], g_vtlo[(size_t)SEQ*HID]; // V^T per head [o][t]
__device__ __align__(256) float g_s[(size_t)NHEADS*SEQ*SEQ];                       // scores fp32
__device__ __align__(256) bf16  g_phi[(size_t)NHEADS*SEQ*SEQ], g_plo[(size_t)NHEADS*SEQ*SEQ];
__device__ __align__(256) bf16  g_ahi[(size_t)SEQ*HID], g_alo[(size_t)SEQ*HID];

// ---------------- small helpers ----------------
__device__ __forceinline__ void split(float v, bf16& h, bf16& l) {
    h = __float2bfloat16(v);
    l = __float2bfloat16(v - __bfloat162float(h));
}
__device__ __forceinline__ uint32_t pack2(bf16 a, bf16 b) {
    uint16_t ua = *(uint16_t*)&a, ub = *(uint16_t*)&b;
    return (uint32_t)ua | ((uint32_t)ub << 16);
}
__device__ __forceinline__ uint32_t smem_u32(const void* p) {
    uint32_t a;
    asm("{ .reg .u64 t; cvta.to.shared.u64 t, %1; cvt.u32.u64 %0, t; }" : "=r"(a) : "l"(p));
    return a;
}

// ---------------- warp-mma + cp.async primitives (baseline PTX, sm_80+) ----------------
__device__ __forceinline__ void ldsm4(uint32_t& r0, uint32_t& r1, uint32_t& r2, uint32_t& r3,
                                      uint32_t addr) {
    asm volatile("ldmatrix.sync.aligned.m8n8.x4.shared.b16 {%0,%1,%2,%3}, [%4];"
                 : "=r"(r0), "=r"(r1), "=r"(r2), "=r"(r3) : "r"(addr));
}
__device__ __forceinline__ void mma16816(float* c, const uint32_t* a, const uint32_t* b) {
    asm volatile(
        "mma.sync.aligned.m16n8k16.row.col.f32.bf16.bf16.f32 "
        "{%0,%1,%2,%3}, {%4,%5,%6,%7}, {%8,%9}, {%0,%1,%2,%3};"
        : "+f"(c[0]), "+f"(c[1]), "+f"(c[2]), "+f"(c[3])
        : "r"(a[0]), "r"(a[1]), "r"(a[2]), "r"(a[3]), "r"(b[0]), "r"(b[1]));
}
__device__ __forceinline__ void cpa16(uint32_t dst, const void* src) {
    asm volatile("cp.async.cg.shared.global [%0], [%1], 16;" :: "r"(dst), "l"(src));
}
#define CP_COMMIT() asm volatile("cp.async.commit_group;" ::: "memory")
#define CP_WAIT(n)  asm volatile("cp.async.wait_group %0;" :: "n"(n) : "memory")

// ---------------- quantize: w -> ternary*scale -> bf16 hi/lo ----------------
__global__ void quantize_kernel(const float* __restrict__ w0, const float* __restrict__ w1,
                                const float* __restrict__ w2, const float* __restrict__ w3) {
    const float* srcs[4] = {w0, w1, w2, w3};
    const float* w = srcs[blockIdx.y];
    bf16* ohi = g_whi[blockIdx.y];
    bf16* olo = g_wlo[blockIdx.y];
    int warp = threadIdx.x >> 5, lane = threadIdx.x & 31;
    size_t g = (size_t)blockIdx.x * 8 + warp;
    float4 v = *(const float4*)(w + g * 128 + lane * 4);
    float s = fabsf(v.x) + fabsf(v.y) + fabsf(v.z) + fabsf(v.w);
    #pragma unroll
    for (int o = 16; o; o >>= 1) s += __shfl_xor_sync(0xffffffffu, s, o);
    float scale = fmaxf(s * (1.f / 128.f), 1e-8f);
    float q[4];
    float wn;
    wn = v.x / scale; q[0] = (wn > 0.5f ? scale : (wn < -0.5f ? -scale : 0.f));
    wn = v.y / scale; q[1] = (wn > 0.5f ? scale : (wn < -0.5f ? -scale : 0.f));
    wn = v.z / scale; q[2] = (wn > 0.5f ? scale : (wn < -0.5f ? -scale : 0.f));
    wn = v.w / scale; q[3] = (wn > 0.5f ? scale : (wn < -0.5f ? -scale : 0.f));
    bf16 h[4], l[4];
    #pragma unroll
    for (int i = 0; i < 4; i++) split(q[i], h[i], l[i]);
    *(uint2*)(ohi + g * 128 + lane * 4) = make_uint2(pack2(h[0], h[1]), pack2(h[2], h[3]));
    *(uint2*)(olo + g * 128 + lane * 4) = make_uint2(pack2(l[0], l[1]), pack2(l[2], l[3]));
}

// ---------------- fp32 -> bf16 hi/lo converter (for x) ----------------
__global__ void convert_kernel(const float* __restrict__ src, bf16* __restrict__ hi,
                               bf16* __restrict__ lo) {
    int i = blockIdx.x * 256 + threadIdx.x;
    float4 v = ((const float4*)src)[i];
    bf16 h0,l0,h1,l1,h2,l2,h3,l3;
    split(v.x,h0,l0); split(v.y,h1,l1); split(v.z,h2,l2); split(v.w,h3,l3);
    ((uint2*)hi)[i] = make_uint2(pack2(h0,h1), pack2(h2,h3));
    ((uint2*)lo)[i] = make_uint2(pack2(l0,l1), pack2(l2,l3));
}

// ---------------- RoPE: fp32 q/k -> roped bf16 hi/lo ----------------
__global__ void rope_kernel(const float* __restrict__ qf, const float* __restrict__ kf,
                            bf16* __restrict__ qhi, bf16* __restrict__ qlo,
                            bf16* __restrict__ khi, bf16* __restrict__ klo) {
    int idx = blockIdx.x * blockDim.x + threadIdx.x;
    const float* y = (blockIdx.y == 0) ? qf : kf;
    bf16* oh = (blockIdx.y == 0) ? qhi : khi;
    bf16* ol = (blockIdx.y == 0) ? qlo : klo;
    int j = idx & 63;
    int h = (idx >> 6) & 15;
    int s = idx >> 10;
    float inv = (float)(1.0 / pow(10000.0, (double)j / 64.0));
    float f = (float)s * inv;
    double fd = (double)f;
    float c  = (float)cos(fd);
    float sn = (float)sin(fd);
    size_t p = (size_t)s * HID + h * HDIM + j;
    float x1 = y[p], x2 = y[p + 64];
    float o1 = x1 * c - x2 * sn;
    float o2 = x1 * sn + x2 * c;
    bf16 hh, ll;
    split(o1, hh, ll); oh[p] = hh;      ol[p] = ll;
    split(o2, hh, ll); oh[p + 64] = hh; ol[p + 64] = ll;
}

// ---------------- warp-mma GEMM: C[M,N] = (Ahi+Alo)(Bhi+Blo)^T ----------------
// Both operands K-major row-major [rows, K]. 128x128 CTA tile, K-chunk 32.
// cp.async 4-stage pipeline.
// OUT: 0 = fp32 C, 1 = bf16 hi/lo split C, 2 = bf16 hi/lo split TRANSPOSED C.
#define KC 32
#define ROWB 80                  // padded bytes per smem row (conflict-free ldmatrix)
#define TILEB (128*ROWB)         // 10240 B per operand tile
#define BUFB  (4*TILEB)          // 40960 B per stage (Ahi,Alo,Bhi,Blo)
#define STAGES 4
#define SMEM_SZ (STAGES*BUFB)    // 163840 B

template<int OUT, bool CSKIP, bool CK>
__global__ void __launch_bounds__(256, 1)
gemm_mma(const bf16* __restrict__ Ahi, const bf16* __restrict__ Alo,
         const bf16* __restrict__ Bhi, const bf16* __restrict__ Blo,
         float* __restrict__ Cf, bf16* __restrict__ Chi, bf16* __restrict__ Clo,
         int K, int lda, int ldb, int ldc,
         long long sA, long long sB, long long sC)
{
    int bx = blockIdx.x, by = blockIdx.y, bz = blockIdx.z;
    if (CSKIP && bx > by) return;
    Ahi += (long long)bz * sA;  Alo += (long long)bz * sA;
    Bhi += (long long)bz * sB;  Blo += (long long)bz * sB;
    Cf  += (long long)bz * sC;  Chi += (long long)bz * sC;  Clo += (long long)bz * sC;

    extern __shared__ char smem[];
    uint32_t sb = smem_u32(smem);

    int tid = threadIdx.x;
    int lane = tid & 31, wid = tid >> 5;
    int wm = wid & 1;            // 2 M groups of 64
    int wn = wid >> 1;           // 4 N groups of 32

    int Keff = K;
    if (CK) { int lim = (by + 1) * 128; if (lim < Keff) Keff = lim; }
    int NC = Keff >> 5;

    const bf16* const srcs[4] = {Ahi, Alo, Bhi, Blo};
    const int ldsv[4] = {lda, lda, ldb, ldb};
    const int r0v[4]  = {by*128, by*128, bx*128, bx*128};
    int row0 = tid >> 2, seg = tid & 3;

    // async load of K-chunk c into stage buffer `buf`
    auto issue = [&](int c, int buf) {
        int k0 = c * KC;
        uint32_t bp = sb + buf * BUFB;
        #pragma unroll
        for (int tl = 0; tl < 4; tl++) {
            const bf16* s = srcs[tl]; int ld = ldsv[tl]; int r0 = r0v[tl];
            cpa16(bp + tl*TILEB + row0*ROWB + seg*16,
                  s + (long long)(r0 + row0)      * ld + k0 + seg*8);
            cpa16(bp + tl*TILEB + (row0+64)*ROWB + seg*16,
                  s + (long long)(r0 + row0 + 64) * ld + k0 + seg*8);
        }
    };

    float acc[4][4][4];
    #pragma unroll
    for (int i = 0; i < 4; i++)
        #pragma unroll
        for (int j = 0; j < 4; j++)
            #pragma unroll
            for (int r = 0; r < 4; r++) acc[i][j][r] = 0.f;

    // prologue: stages 0..STAGES-2
    #pragma unroll
    for (int s = 0; s < STAGES-1; s++) {
        if (s < NC) issue(s, s);
        CP_COMMIT();
    }

    uint32_t arow = wm*64 + (lane & 7) + ((lane >> 3) & 1) * 8;   // + mt*16
    uint32_t brow = wn*32 + (lane & 7) + ((lane >> 3) & 1) * 8;   // + np*16
    uint32_t kcol = ((lane >> 4) & 1) * 16;                       // k8 half offset (bytes)

    for (int c = 0; c < NC; c++) {
        int nxt = c + STAGES - 1;
        if (nxt < NC) issue(nxt, nxt % STAGES);
        CP_COMMIT();
        CP_WAIT(STAGES-1);          // stage c landed
        __syncthreads();

        uint32_t base = sb + (c % STAGES) * BUFB;
        #pragma unroll
        for (int ks = 0; ks < 2; ks++) {
            uint32_t af[2][4][4];
            uint32_t bfr[2][4][2];
            #pragma unroll
            for (int mt = 0; mt < 4; mt++) {
                uint32_t ra = base + (arow + mt*16) * ROWB + ks*32 + kcol;
                ldsm4(af[0][mt][0], af[0][mt][1], af[0][mt][2], af[0][mt][3], ra);
                ldsm4(af[1][mt][0], af[1][mt][1], af[1][mt][2], af[1][mt][3], ra + TILEB);
            }
            #pragma unroll
            for (int np = 0; np < 2; np++) {
                // B is K-major [N,K]: NON-trans ldmatrix yields the mma B fragment.
                uint32_t rb = base + 2*TILEB + (brow + np*16) * ROWB + ks*32 + kcol;
                uint32_t r0, r1, r2, r3;
                ldsm4(r0, r1, r2, r3, rb);
                bfr[0][np*2][0] = r0;   bfr[0][np*2][1]   = r2;
                bfr[0][np*2+1][0] = r1; bfr[0][np*2+1][1] = r3;
                ldsm4(r0, r1, r2, r3, rb + TILEB);
                bfr[1][np*2][0] = r0;   bfr[1][np*2][1]   = r2;
                bfr[1][np*2+1][0] = r1; bfr[1][np*2+1][1] = r3;
            }
            #pragma unroll
            for (int mt = 0; mt < 4; mt++)
                #pragma unroll
                for (int nt = 0; nt < 4; nt++) {
                    mma16816(acc[mt][nt], af[0][mt], bfr[0][nt]);  // hi*hi
                    mma16816(acc[mt][nt], af[0][mt], bfr[1][nt]);  // hi*lo
                    mma16816(acc[mt][nt], af[1][mt], bfr[0][nt]);  // lo*hi
                }
        }
        __syncthreads();   // stage buffer reusable by issue() of a later chunk
    }

    // ---------------- epilogue ----------------
    int tg = lane >> 2, t4 = lane & 3;
    if (OUT == 2) {
        // stage transposed tile through smem, write coalesced. pad rows to 136 bf16.
        const int TP = 136;
        bf16* tbuf = (bf16*)smem;
        #pragma unroll
        for (int pass = 0; pass < 2; pass++) {
            #pragma unroll
            for (int mt = 0; mt < 4; mt++)
                #pragma unroll
                for (int rp = 0; rp < 2; rp++) {
                    int ml = wm*64 + mt*16 + tg + rp*8;
                    #pragma unroll
                    for (int nt = 0; nt < 4; nt++) {
                        int cl = wn*32 + nt*8 + t4*2;
                        float c0 = acc[mt][nt][rp*2+0], c1 = acc[mt][nt][rp*2+1];
                        bf16 h0, l0, h1, l1;
                        split(c0, h0, l0); split(c1, h1, l1);
                        tbuf[(cl+0)*TP + ml] = pass ? l0 : h0;
                        tbuf[(cl+1)*TP + ml] = pass ? l1 : h1;
                    }
                }
            __syncthreads();
            {
                int row = tid >> 1, part = tid & 1;         // 128 rows x 2 halves
                bf16* dst = (pass ? Clo : Chi) + (long long)(bx*128 + row) * ldc + by*128 + part*64;
                const uint4* s4 = (const uint4*)(tbuf + row*TP + part*64);
                uint4* d4 = (uint4*)dst;
                #pragma unroll
                for (int j = 0; j < 8; j++) d4[j] = s4[j];
            }
            __syncthreads();
        }
        return;
    }
    #pragma unroll
    for (int mt = 0; mt < 4; mt++)
        #pragma unroll
        for (int rp = 0; rp < 2; rp++) {
            int m = by*128 + wm*64 + mt*16 + tg + rp*8;
            #pragma unroll
            for (int nt = 0; nt < 4; nt++) {
                int col = bx*128 + wn*32 + nt*8 + t4*2;
                float c0 = acc[mt][nt][rp*2+0], c1 = acc[mt][nt][rp*2+1];
                if (OUT == 0) {
                    *(float2*)(Cf + (long long)m * ldc + col) = make_float2(c0, c1);
                } else {
                    bf16 h0,l0,h1,l1;
                    split(c0, h0, l0); split(c1, h1, l1);
                    *(uint32_t*)(Chi + (long long)m * ldc + col) = pack2(h0, h1);
                    *(uint32_t*)(Clo + (long long)m * ldc + col) = pack2(l0, l1);
                }
            }
        }
}

// ---------------- softmax: fp32 scores -> bf16 hi/lo probs ----------------
__device__ __forceinline__ float blockReduce(float v, bool isMax) {
    __shared__ float sh[8];
    #pragma unroll
    for (int o = 16; o; o >>= 1) {
        float t = __shfl_xor_sync(0xffffffffu, v, o);
        v = isMax ? fmaxf(v, t) : (v + t);
    }
    int w = threadIdx.x >> 5, l = threadIdx.x & 31;
    if (l == 0) sh[w] = v;
    __syncthreads();
    if (w == 0) {
        float t = (l < 8) ? sh[l] : (isMax ? -INFINITY : 0.f);
        #pragma unroll
        for (int o = 4; o; o >>= 1) {
            float u = __shfl_xor_sync(0xffffffffu, t, o);
            t = isMax ? fmaxf(t, u) : (t + u);
        }
        if (l == 0) sh[0] = t;
    }
    __syncthreads();
    float r = sh[0];
    __syncthreads();
    return r;
}

__global__ void softmax_kernel(float* __restrict__ scores, const int* __restrict__ mask,
                               bf16* __restrict__ phi, bf16* __restrict__ plo) {
    int s = blockIdx.x, h = blockIdx.y;
    size_t rbase = ((size_t)h * SEQ + s) * SEQ;
    float* row = scores + rbase;
    int valid = s + 1;
    const float scale = 0.088388347648318447f;   // 1/sqrt(128)
    float mx = -INFINITY;
    for (int t = threadIdx.x; t < valid; t += blockDim.x)
        if (mask[t] != 0) mx = fmaxf(mx, row[t] * scale);
    mx = blockReduce(mx, true);
    float sum = 0.f;
    for (int t = threadIdx.x; t < valid; t += blockDim.x) {
        float e = (mask[t] != 0) ? expf(row[t] * scale - mx) : 0.f;
        row[t] = e;
        sum += e;
    }
    sum = blockReduce(sum, false);
    float invsum = 1.f / sum;
    for (int t = threadIdx.x; t < valid; t += blockDim.x) {
        float p = row[t] * invsum;
        bf16 hh, ll; split(p, hh, ll);
        phi[rbase + t] = hh; plo[rbase + t] = ll;
    }
    int zend = ((s >> 7) + 1) << 7;              // zero-fill through diagonal 128-block
    bf16 z = __float2bfloat16(0.f);
    for (int t = valid + threadIdx.x; t < zend; t += blockDim.x) {
        phi[rbase + t] = z; plo[rbase + t] = z;
    }
}

// ---------------- launch ----------------
extern "C" void kernel_launch(void* const* d_in, const int* in_sizes, int n_in,
                              void* d_out, int out_size) {
    const float* x    = (const float*)d_in[0];
    const int*   mask = (const int*)d_in[1];
    const float* wq   = (const float*)d_in[2];
    const float* wk   = (const float*)d_in[3];
    const float* wv   = (const float*)d_in[4];
    const float* wo   = (const float*)d_in[5];

    bf16 *xhi, *xlo, *whi, *wlo, *qhi, *qlo, *khi, *klo, *vthi, *vtlo, *phi, *plo, *ahi, *alo;
    float *qf, *kf, *sc;
    cudaGetSymbolAddress((void**)&xhi,  g_xhi);  cudaGetSymbolAddress((void**)&xlo,  g_xlo);
    cudaGetSymbolAddress((void**)&whi,  g_whi);  cudaGetSymbolAddress((void**)&wlo,  g_wlo);
    cudaGetSymbolAddress((void**)&qf,   g_qf);   cudaGetSymbolAddress((void**)&kf,   g_kf);
    cudaGetSymbolAddress((void**)&qhi,  g_qhi);  cudaGetSymbolAddress((void**)&qlo,  g_qlo);
    cudaGetSymbolAddress((void**)&khi,  g_khi);  cudaGetSymbolAddress((void**)&klo,  g_klo);
    cudaGetSymbolAddress((void**)&vthi, g_vthi); cudaGetSymbolAddress((void**)&vtlo, g_vtlo);
    cudaGetSymbolAddress((void**)&sc,   g_s);
    cudaGetSymbolAddress((void**)&phi,  g_phi);  cudaGetSymbolAddress((void**)&plo,  g_plo);
    cudaGetSymbolAddress((void**)&ahi,  g_ahi);  cudaGetSymbolAddress((void**)&alo,  g_alo);

    const size_t WSZ = (size_t)HID * HID;

    cudaFuncSetAttribute(gemm_mma<0,false,false>, cudaFuncAttributeMaxDynamicSharedMemorySize, SMEM_SZ);
    cudaFuncSetAttribute(gemm_mma<2,false,false>, cudaFuncAttributeMaxDynamicSharedMemorySize, SMEM_SZ);
    cudaFuncSetAttribute(gemm_mma<0,true, false>, cudaFuncAttributeMaxDynamicSharedMemorySize, SMEM_SZ);
    cudaFuncSetAttribute(gemm_mma<1,false,true >, cudaFuncAttributeMaxDynamicSharedMemorySize, SMEM_SZ);

    // 1. quantize weights -> bf16 hi/lo
    quantize_kernel<<<dim3(GROUPS_PER_W / 8, 4), 256>>>(wq, wk, wv, wo);

    // 2. x -> bf16 hi/lo
    convert_kernel<<<(SEQ * HID / 4) / 256, 256>>>(x, xhi, xlo);

    // 3. projections
    dim3 g16(16, 16, 1);
    gemm_mma<0,false,false><<<g16, 256, SMEM_SZ>>>(xhi, xlo, whi,           wlo,           qf, 0, 0,
                                                   HID, HID, HID, HID, 0, 0, 0);
    gemm_mma<0,false,false><<<g16, 256, SMEM_SZ>>>(xhi, xlo, whi + WSZ,     wlo + WSZ,     kf, 0, 0,
                                                   HID, HID, HID, HID, 0, 0, 0);
    // V projection -> transposed split [o][t]
    gemm_mma<2,false,false><<<g16, 256, SMEM_SZ>>>(xhi, xlo, whi + 2 * WSZ, wlo + 2 * WSZ, 0, vthi, vtlo,
                                                   HID, HID, HID, SEQ, 0, 0, 0);

    // 4. RoPE -> bf16 hi/lo
    rope_kernel<<<dim3(SEQ * NHEADS * 64 / 256, 2), 256>>>(qf, kf, qhi, qlo, khi, klo);

    // 5. scores = Q K^T per head (causal block skip), fp32 out
    gemm_mma<0,true,false><<<dim3(16, 16, NHEADS), 256, SMEM_SZ>>>(
        qhi, qlo, khi, klo, sc, 0, 0,
        HDIM, HID, HID, SEQ, /*sA=*/HDIM, /*sB=*/HDIM, /*sC=*/(long long)SEQ * SEQ);

    // 6. softmax -> P bf16 hi/lo (zero-filled through diagonal block)
    softmax_kernel<<<dim3(SEQ, NHEADS), 256>>>(sc, mask, phi, plo);

    // 7. attn = P V per head (causal K-limit), split out into [s, h*128+d]
    gemm_mma<1,false,true><<<dim3(1, 16, NHEADS), 256, SMEM_SZ>>>(
        phi, plo, vthi, vtlo, 0, ahi, alo,
        SEQ, SEQ, SEQ, HID, /*sA=*/(long long)SEQ * SEQ, /*sB=*/(long long)HDIM * SEQ, /*sC=*/HDIM);

    // 8. out = attn @ Wo^T -> d_out
    gemm_mma<0,false,false><<<g16, 256, SMEM_SZ>>>(ahi, alo, whi + 3 * WSZ, wlo + 3 * WSZ,
                                                   (float*)d_out, 0, 0,
                                                   HID, HID, HID, HID, 0, 0, 0);
}

// round 11
// speedup vs baseline: 1.5092x; 1.5092x over previous
#include <cuda_runtime.h>
#include <cuda_bf16.h>
#include <stdint.h>
#include <math.h>

#define HID 2048
#define SEQ 2048
#define NHEADS 16
#define HDIM 128
#define GROUPS_PER_W (HID*HID/128)

typedef __nv_bfloat16 bf16;

// ---------------- scratch (static device memory; no allocation) ----------------
__device__ __align__(256) bf16  g_xhi[(size_t)SEQ*HID],  g_xlo[(size_t)SEQ*HID];
__device__ __align__(256) bf16  g_whi[4][(size_t)HID*HID], g_wlo[4][(size_t)HID*HID];
__device__ __align__(256) float g_qf[(size_t)SEQ*HID],  g_kf[(size_t)SEQ*HID];
__device__ __align__(256) bf16  g_qhi[(size_t)SEQ*HID], g_qlo[(size_t)SEQ*HID];
__device__ __align__(256) bf16  g_khi[(size_t)SEQ*HID], g_klo[(size_t)SEQ*HID];
__device__ __align__(256) bf16  g_vthi[(size_t)SEQ*HID], g_vtlo[(size_t)SEQ*HID]; // V^T per head [d][t]
__device__ __align__(256) bf16  g_ahi[(size_t)SEQ*HID], g_alo[(size_t)SEQ*HID];

// ---------------- small helpers ----------------
__device__ __forceinline__ void split(float v, bf16& h, bf16& l) {
    h = __float2bfloat16(v);
    l = __float2bfloat16(v - __bfloat162float(h));
}
__device__ __forceinline__ uint32_t pack2(bf16 a, bf16 b) {
    uint16_t ua = *(uint16_t*)&a, ub = *(uint16_t*)&b;
    return (uint32_t)ua | ((uint32_t)ub << 16);
}
__device__ __forceinline__ uint32_t smem_u32(const void* p) {
    uint32_t a;
    asm("{ .reg .u64 t; cvta.to.shared.u64 t, %1; cvt.u32.u64 %0, t; }" : "=r"(a) : "l"(p));
    return a;
}

// ---------------- warp-mma primitives (baseline PTX, sm_80+) ----------------
__device__ __forceinline__ void ldsm4(uint32_t& r0, uint32_t& r1, uint32_t& r2, uint32_t& r3,
                                      uint32_t addr) {
    asm volatile("ldmatrix.sync.aligned.m8n8.x4.shared.b16 {%0,%1,%2,%3}, [%4];"
                 : "=r"(r0), "=r"(r1), "=r"(r2), "=r"(r3) : "r"(addr));
}
__device__ __forceinline__ void mma16816(float* c, const uint32_t* a, const uint32_t* b) {
    asm volatile(
        "mma.sync.aligned.m16n8k16.row.col.f32.bf16.bf16.f32 "
        "{%0,%1,%2,%3}, {%4,%5,%6,%7}, {%8,%9}, {%0,%1,%2,%3};"
        : "+f"(c[0]), "+f"(c[1]), "+f"(c[2]), "+f"(c[3])
        : "r"(a[0]), "r"(a[1]), "r"(a[2]), "r"(a[3]), "r"(b[0]), "r"(b[1]));
}

// ---------------- quantize: w -> ternary*scale -> bf16 hi/lo ----------------
__global__ void quantize_kernel(const float* __restrict__ w0, const float* __restrict__ w1,
                                const float* __restrict__ w2, const float* __restrict__ w3) {
    const float* srcs[4] = {w0, w1, w2, w3};
    const float* w = srcs[blockIdx.y];
    bf16* ohi = g_whi[blockIdx.y];
    bf16* olo = g_wlo[blockIdx.y];
    int warp = threadIdx.x >> 5, lane = threadIdx.x & 31;
    size_t g = (size_t)blockIdx.x * 8 + warp;
    float4 v = *(const float4*)(w + g * 128 + lane * 4);
    float s = fabsf(v.x) + fabsf(v.y) + fabsf(v.z) + fabsf(v.w);
    #pragma unroll
    for (int o = 16; o; o >>= 1) s += __shfl_xor_sync(0xffffffffu, s, o);
    float scale = fmaxf(s * (1.f / 128.f), 1e-8f);
    float q[4];
    float wn;
    wn = v.x / scale; q[0] = (wn > 0.5f ? scale : (wn < -0.5f ? -scale : 0.f));
    wn = v.y / scale; q[1] = (wn > 0.5f ? scale : (wn < -0.5f ? -scale : 0.f));
    wn = v.z / scale; q[2] = (wn > 0.5f ? scale : (wn < -0.5f ? -scale : 0.f));
    wn = v.w / scale; q[3] = (wn > 0.5f ? scale : (wn < -0.5f ? -scale : 0.f));
    bf16 h[4], l[4];
    #pragma unroll
    for (int i = 0; i < 4; i++) split(q[i], h[i], l[i]);
    *(uint2*)(ohi + g * 128 + lane * 4) = make_uint2(pack2(h[0], h[1]), pack2(h[2], h[3]));
    *(uint2*)(olo + g * 128 + lane * 4) = make_uint2(pack2(l[0], l[1]), pack2(l[2], l[3]));
}

// ---------------- fp32 -> bf16 hi/lo converter (for x) ----------------
__global__ void convert_kernel(const float* __restrict__ src, bf16* __restrict__ hi,
                               bf16* __restrict__ lo) {
    int i = blockIdx.x * 256 + threadIdx.x;
    float4 v = ((const float4*)src)[i];
    bf16 h0,l0,h1,l1,h2,l2,h3,l3;
    split(v.x,h0,l0); split(v.y,h1,l1); split(v.z,h2,l2); split(v.w,h3,l3);
    ((uint2*)hi)[i] = make_uint2(pack2(h0,h1), pack2(h2,h3));
    ((uint2*)lo)[i] = make_uint2(pack2(l0,l1), pack2(l2,l3));
}

// ---------------- RoPE: fp32 q/k -> roped bf16 hi/lo ----------------
__global__ void rope_kernel(const float* __restrict__ qf, const float* __restrict__ kf,
                            bf16* __restrict__ qhi, bf16* __restrict__ qlo,
                            bf16* __restrict__ khi, bf16* __restrict__ klo) {
    int idx = blockIdx.x * blockDim.x + threadIdx.x;
    const float* y = (blockIdx.y == 0) ? qf : kf;
    bf16* oh = (blockIdx.y == 0) ? qhi : khi;
    bf16* ol = (blockIdx.y == 0) ? qlo : klo;
    int j = idx & 63;
    int h = (idx >> 6) & 15;
    int s = idx >> 10;
    float inv = (float)(1.0 / pow(10000.0, (double)j / 64.0));
    float f = (float)s * inv;
    double fd = (double)f;
    float c  = (float)cos(fd);
    float sn = (float)sin(fd);
    size_t p = (size_t)s * HID + h * HDIM + j;
    float x1 = y[p], x2 = y[p + 64];
    float o1 = x1 * c - x2 * sn;
    float o2 = x1 * sn + x2 * c;
    bf16 hh, ll;
    split(o1, hh, ll); oh[p] = hh;      ol[p] = ll;
    split(o2, hh, ll); oh[p + 64] = hh; ol[p + 64] = ll;
}

// ---------------- warp-mma GEMM (round-9 engine): C = (Ahi+Alo)(Bhi+Blo)^T ----------------
// OUT: 0 = fp32 C, 2 = bf16 hi/lo split TRANSPOSED C.
#define KC 32
#define ROWB 80
#define TILEB (128*ROWB)
#define BUFB  (4*TILEB)
#define SMEM_SZ (2*BUFB)

template<int OUT>
__global__ void __launch_bounds__(256, 1)
gemm_mma(const bf16* __restrict__ Ahi, const bf16* __restrict__ Alo,
         const bf16* __restrict__ Bhi, const bf16* __restrict__ Blo,
         float* __restrict__ Cf, bf16* __restrict__ Chi, bf16* __restrict__ Clo,
         int K, int lda, int ldb, int ldc)
{
    int bx = blockIdx.x, by = blockIdx.y;

    extern __shared__ char smem[];
    uint32_t sb = smem_u32(smem);

    int tid = threadIdx.x;
    int lane = tid & 31, wid = tid >> 5;
    int wm = wid & 1;
    int wn = wid >> 1;

    int NC = K >> 5;

    const bf16* const srcs[4] = {Ahi, Alo, Bhi, Blo};
    const int ldsv[4] = {lda, lda, ldb, ldb};
    const int r0v[4]  = {by*128, by*128, bx*128, bx*128};
    int row0 = tid >> 2, seg = tid & 3;

    uint4 stg[8];
    auto ldg = [&](int c) {
        int k0 = c * KC;
        #pragma unroll
        for (int tl = 0; tl < 4; tl++) {
            const bf16* s = srcs[tl]; int ld = ldsv[tl]; int r0 = r0v[tl];
            stg[tl*2+0] = *(const uint4*)(s + (long long)(r0 + row0)      * ld + k0 + seg*8);
            stg[tl*2+1] = *(const uint4*)(s + (long long)(r0 + row0 + 64) * ld + k0 + seg*8);
        }
    };
    auto sts = [&](int buf) {
        char* bp = smem + buf * BUFB;
        #pragma unroll
        for (int tl = 0; tl < 4; tl++) {
            *(uint4*)(bp + tl*TILEB + row0*ROWB + seg*16)        = stg[tl*2+0];
            *(uint4*)(bp + tl*TILEB + (row0+64)*ROWB + seg*16)   = stg[tl*2+1];
        }
    };

    float acc[4][4][4];
    #pragma unroll
    for (int i = 0; i < 4; i++)
        #pragma unroll
        for (int j = 0; j < 4; j++)
            #pragma unroll
            for (int r = 0; r < 4; r++) acc[i][j][r] = 0.f;

    ldg(0); sts(0); __syncthreads();

    uint32_t arow = wm*64 + (lane & 7) + ((lane >> 3) & 1) * 8;
    uint32_t brow = wn*32 + (lane & 7) + ((lane >> 3) & 1) * 8;
    uint32_t kcol = ((lane >> 4) & 1) * 16;

    for (int c = 0; c < NC; c++) {
        int cb = c & 1, nb = (c + 1) & 1;
        bool pf = (c + 1 < NC);
        if (pf) ldg(c + 1);

        uint32_t base = sb + cb * BUFB;
        #pragma unroll
        for (int ks = 0; ks < 2; ks++) {
            uint32_t af[2][4][4];
            uint32_t bfr[2][4][2];
            #pragma unroll
            for (int mt = 0; mt < 4; mt++) {
                uint32_t ra = base + (arow + mt*16) * ROWB + ks*32 + kcol;
                ldsm4(af[0][mt][0], af[0][mt][1], af[0][mt][2], af[0][mt][3], ra);
                ldsm4(af[1][mt][0], af[1][mt][1], af[1][mt][2], af[1][mt][3], ra + TILEB);
            }
            #pragma unroll
            for (int np = 0; np < 2; np++) {
                uint32_t rb = base + 2*TILEB + (brow + np*16) * ROWB + ks*32 + kcol;
                uint32_t r0, r1, r2, r3;
                ldsm4(r0, r1, r2, r3, rb);
                bfr[0][np*2][0] = r0;   bfr[0][np*2][1]   = r2;
                bfr[0][np*2+1][0] = r1; bfr[0][np*2+1][1] = r3;
                ldsm4(r0, r1, r2, r3, rb + TILEB);
                bfr[1][np*2][0] = r0;   bfr[1][np*2][1]   = r2;
                bfr[1][np*2+1][0] = r1; bfr[1][np*2+1][1] = r3;
            }
            #pragma unroll
            for (int mt = 0; mt < 4; mt++)
                #pragma unroll
                for (int nt = 0; nt < 4; nt++) {
                    mma16816(acc[mt][nt], af[0][mt], bfr[0][nt]);
                    mma16816(acc[mt][nt], af[0][mt], bfr[1][nt]);
                    mma16816(acc[mt][nt], af[1][mt], bfr[0][nt]);
                }
        }
        __syncthreads();
        if (pf) { sts(nb); __syncthreads(); }
    }

    int tg = lane >> 2, t4 = lane & 3;
    #pragma unroll
    for (int mt = 0; mt < 4; mt++)
        #pragma unroll
        for (int rp = 0; rp < 2; rp++) {
            int m = by*128 + wm*64 + mt*16 + tg + rp*8;
            #pragma unroll
            for (int nt = 0; nt < 4; nt++) {
                int col = bx*128 + wn*32 + nt*8 + t4*2;
                float c0 = acc[mt][nt][rp*2+0], c1 = acc[mt][nt][rp*2+1];
                if (OUT == 0) {
                    *(float2*)(Cf + (long long)m * ldc + col) = make_float2(c0, c1);
                } else {
                    bf16 h0,l0,h1,l1;
                    split(c0, h0, l0); split(c1, h1, l1);
                    Chi[(long long)col * ldc + m] = h0;       Clo[(long long)col * ldc + m] = l0;
                    Chi[(long long)(col+1) * ldc + m] = h1;   Clo[(long long)(col+1) * ldc + m] = l1;
                }
            }
        }
}

// ---------------- fused flash attention ----------------
// grid (16 qblocks, 16 heads), 256 threads. Warp w owns query rows w*16..w*16+15.
// SMEM: Q hi/lo resident; K hi/lo + V^T hi/lo staged per key block. Row stride 272B.
#define AQ    0
#define AQLO  34816
#define AKHI  69632
#define AKLO  104448
#define AVHI  139264
#define AVLO  174080
#define AMSK  208896
#define ASMEM 209920

__global__ void __launch_bounds__(256, 1)
attn_kernel(const bf16* __restrict__ qhi, const bf16* __restrict__ qlo,
            const bf16* __restrict__ khi, const bf16* __restrict__ klo,
            const bf16* __restrict__ vthi, const bf16* __restrict__ vtlo,
            const int* __restrict__ mask,
            bf16* __restrict__ ahi, bf16* __restrict__ alo)
{
    int qb = 15 - (int)blockIdx.x;       // longest-running CTAs first
    int h  = blockIdx.y;
    extern __shared__ char smem[];
    uint32_t sb = smem_u32(smem);
    int tid = threadIdx.x, lane = tid & 31, wid = tid >> 5;
    int tg = lane >> 2, t4 = lane & 3;

    // resident Q tiles (hi & lo): 128 rows x 128 cols
    {
        int r = tid >> 1, cb = (tid & 1) * 64;
        const uint4* s0 = (const uint4*)(qhi + (size_t)(qb*128 + r)*HID + h*128 + cb);
        const uint4* s1 = (const uint4*)(qlo + (size_t)(qb*128 + r)*HID + h*128 + cb);
        uint4* d0 = (uint4*)(smem + AQ   + r*272 + cb*2);
        uint4* d1 = (uint4*)(smem + AQLO + r*272 + cb*2);
        #pragma unroll
        for (int j = 0; j < 8; j++) { d0[j] = s0[j]; d1[j] = s1[j]; }
    }

    float o[16][4];
    #pragma unroll
    for (int i = 0; i < 16; i++)
        #pragma unroll
        for (int j = 0; j < 4; j++) o[i][j] = 0.f;
    float m0 = -INFINITY, m1 = -INFINITY, l0 = 0.f, l1 = 0.f;

    uint32_t lrow = (lane & 7) + ((lane >> 3) & 1) * 8;
    uint32_t kcol = ((lane >> 4) & 1) * 16;
    uint32_t arow = sb + AQ + (wid*16 + lrow) * 272 + kcol;
    uint32_t broff = lrow * 272 + kcol;
    int rowg0 = qb*128 + wid*16 + tg;     // this thread's rows: rowg0, rowg0+8
    const float SC = 0.088388347648318447f;   // 1/sqrt(128)

    for (int tb = 0; tb <= qb; tb++) {
        __syncthreads();                  // previous block's smem reads done
        {
            int r = tid >> 1, cb = (tid & 1) * 64;
            const uint4* s0 = (const uint4*)(khi  + (size_t)(tb*128 + r)*HID + h*128 + cb);
            const uint4* s1 = (const uint4*)(klo  + (size_t)(tb*128 + r)*HID + h*128 + cb);
            const uint4* s2 = (const uint4*)(vthi + (size_t)(h*128 + r)*SEQ + tb*128 + cb);
            const uint4* s3 = (const uint4*)(vtlo + (size_t)(h*128 + r)*SEQ + tb*128 + cb);
            uint4* d0 = (uint4*)(smem + AKHI + r*272 + cb*2);
            uint4* d1 = (uint4*)(smem + AKLO + r*272 + cb*2);
            uint4* d2 = (uint4*)(smem + AVHI + r*272 + cb*2);
            uint4* d3 = (uint4*)(smem + AVLO + r*272 + cb*2);
            #pragma unroll
            for (int j = 0; j < 8; j++) { d0[j] = s0[j]; d1[j] = s1[j]; d2[j] = s2[j]; d3[j] = s3[j]; }
            if (tid < 128) ((int*)(smem + AMSK))[tid] = mask[tb*128 + tid];
        }
        __syncthreads();

        // ---- S = Q K^T (warp: 16 rows x 128 cols) ----
        float s[16][4];
        #pragma unroll
        for (int i = 0; i < 16; i++)
            #pragma unroll
            for (int j = 0; j < 4; j++) s[i][j] = 0.f;

        #pragma unroll
        for (int ks = 0; ks < 8; ks++) {
            uint32_t ah[4], al[4];
            ldsm4(ah[0], ah[1], ah[2], ah[3], arow + ks*32);
            ldsm4(al[0], al[1], al[2], al[3], arow + ks*32 + (AQLO - AQ));
            #pragma unroll
            for (int np = 0; np < 8; np++) {
                uint32_t rb = sb + AKHI + np*16*272 + broff + ks*32;
                uint32_t r0, r1, r2, r3;
                ldsm4(r0, r1, r2, r3, rb);
                uint32_t bh0[2] = {r0, r2}, bh1[2] = {r1, r3};
                ldsm4(r0, r1, r2, r3, rb + (AKLO - AKHI));
                uint32_t bl0[2] = {r0, r2}, bl1[2] = {r1, r3};
                mma16816(s[2*np],   ah, bh0); mma16816(s[2*np],   ah, bl0); mma16816(s[2*np],   al, bh0);
                mma16816(s[2*np+1], ah, bh1); mma16816(s[2*np+1], ah, bl1); mma16816(s[2*np+1], al, bh1);
            }
        }

        // ---- scale + causal + pad mask, row max ----
        const int* mk = (const int*)(smem + AMSK);
        float mx0 = -INFINITY, mx1 = -INFINITY;
        #pragma unroll
        for (int nt = 0; nt < 16; nt++) {
            int cl = nt*8 + t4*2;
            int cg = tb*128 + cl;
            bool v0 = (mk[cl] != 0), v1 = (mk[cl+1] != 0);
            s[nt][0] = (v0 && cg     <= rowg0    ) ? s[nt][0]*SC : -INFINITY;
            s[nt][1] = (v1 && cg + 1 <= rowg0    ) ? s[nt][1]*SC : -INFINITY;
            s[nt][2] = (v0 && cg     <= rowg0 + 8) ? s[nt][2]*SC : -INFINITY;
            s[nt][3] = (v1 && cg + 1 <= rowg0 + 8) ? s[nt][3]*SC : -INFINITY;
            mx0 = fmaxf(mx0, fmaxf(s[nt][0], s[nt][1]));
            mx1 = fmaxf(mx1, fmaxf(s[nt][2], s[nt][3]));
        }
        mx0 = fmaxf(mx0, __shfl_xor_sync(0xffffffffu, mx0, 1));
        mx0 = fmaxf(mx0, __shfl_xor_sync(0xffffffffu, mx0, 2));
        mx1 = fmaxf(mx1, __shfl_xor_sync(0xffffffffu, mx1, 1));
        mx1 = fmaxf(mx1, __shfl_xor_sync(0xffffffffu, mx1, 2));

        float mn0 = fmaxf(m0, mx0), mn1 = fmaxf(m1, mx1);
        float base0 = (mn0 == -INFINITY) ? 0.f : mn0;
        float base1 = (mn1 == -INFINITY) ? 0.f : mn1;
        float f0 = expf(m0 - base0);     // m0=-INF -> 0
        float f1 = expf(m1 - base1);
        m0 = mn0; m1 = mn1;

        float sum0 = 0.f, sum1 = 0.f;
        #pragma unroll
        for (int nt = 0; nt < 16; nt++) {
            s[nt][0] = expf(s[nt][0] - base0);
            s[nt][1] = expf(s[nt][1] - base0);
            s[nt][2] = expf(s[nt][2] - base1);
            s[nt][3] = expf(s[nt][3] - base1);
            sum0 += s[nt][0] + s[nt][1];
            sum1 += s[nt][2] + s[nt][3];
        }
        sum0 += __shfl_xor_sync(0xffffffffu, sum0, 1);
        sum0 += __shfl_xor_sync(0xffffffffu, sum0, 2);
        sum1 += __shfl_xor_sync(0xffffffffu, sum1, 1);
        sum1 += __shfl_xor_sync(0xffffffffu, sum1, 2);
        l0 = l0 * f0 + sum0;
        l1 = l1 * f1 + sum1;

        #pragma unroll
        for (int dn = 0; dn < 16; dn++) {
            o[dn][0] *= f0; o[dn][1] *= f0;
            o[dn][2] *= f1; o[dn][3] *= f1;
        }

        // ---- O += P V  (P from registers: C fragment == A fragment layout) ----
        #pragma unroll
        for (int ks = 0; ks < 8; ks++) {
            uint32_t aph[4], apl[4];
            {
                bf16 hh[8], ll[8];
                split(s[2*ks][0], hh[0], ll[0]); split(s[2*ks][1], hh[1], ll[1]);
                split(s[2*ks][2], hh[2], ll[2]); split(s[2*ks][3], hh[3], ll[3]);
                split(s[2*ks+1][0], hh[4], ll[4]); split(s[2*ks+1][1], hh[5], ll[5]);
                split(s[2*ks+1][2], hh[6], ll[6]); split(s[2*ks+1][3], hh[7], ll[7]);
                aph[0] = pack2(hh[0], hh[1]); aph[1] = pack2(hh[2], hh[3]);
                aph[2] = pack2(hh[4], hh[5]); aph[3] = pack2(hh[6], hh[7]);
                apl[0] = pack2(ll[0], ll[1]); apl[1] = pack2(ll[2], ll[3]);
                apl[2] = pack2(ll[4], ll[5]); apl[3] = pack2(ll[6], ll[7]);
            }
            #pragma unroll
            for (int np = 0; np < 8; np++) {
                uint32_t rb = sb + AVHI + np*16*272 + broff + ks*32;
                uint32_t r0, r1, r2, r3;
                ldsm4(r0, r1, r2, r3, rb);
                uint32_t vh0[2] = {r0, r2}, vh1[2] = {r1, r3};
                ldsm4(r0, r1, r2, r3, rb + (AVLO - AVHI));
                uint32_t vl0[2] = {r0, r2}, vl1[2] = {r1, r3};
                mma16816(o[2*np],   aph, vh0); mma16816(o[2*np],   aph, vl0); mma16816(o[2*np],   apl, vh0);
                mma16816(o[2*np+1], aph, vh1); mma16816(o[2*np+1], aph, vl1); mma16816(o[2*np+1], apl, vh1);
            }
        }
    }

    // ---- epilogue: O /= l, split to ahi/alo [s, h*128+d] ----
    float i0 = 1.f / l0, i1 = 1.f / l1;
    int mrow = qb*128 + wid*16 + tg;
    #pragma unroll
    for (int dn = 0; dn < 16; dn++) {
        int col = h*128 + dn*8 + t4*2;
        bf16 h0, q0, h1, q1;
        split(o[dn][0]*i0, h0, q0); split(o[dn][1]*i0, h1, q1);
        *(uint32_t*)(ahi + (size_t)mrow*HID + col) = pack2(h0, h1);
        *(uint32_t*)(alo + (size_t)mrow*HID + col) = pack2(q0, q1);
        split(o[dn][2]*i1, h0, q0); split(o[dn][3]*i1, h1, q1);
        *(uint32_t*)(ahi + (size_t)(mrow+8)*HID + col) = pack2(h0, h1);
        *(uint32_t*)(alo + (size_t)(mrow+8)*HID + col) = pack2(q0, q1);
    }
}

// ---------------- launch ----------------
extern "C" void kernel_launch(void* const* d_in, const int* in_sizes, int n_in,
                              void* d_out, int out_size) {
    const float* x    = (const float*)d_in[0];
    const int*   mask = (const int*)d_in[1];
    const float* wq   = (const float*)d_in[2];
    const float* wk   = (const float*)d_in[3];
    const float* wv   = (const float*)d_in[4];
    const float* wo   = (const float*)d_in[5];

    bf16 *xhi, *xlo, *whi, *wlo, *qhi, *qlo, *khi, *klo, *vthi, *vtlo, *ahi, *alo;
    float *qf, *kf;
    cudaGetSymbolAddress((void**)&xhi,  g_xhi);  cudaGetSymbolAddress((void**)&xlo,  g_xlo);
    cudaGetSymbolAddress((void**)&whi,  g_whi);  cudaGetSymbolAddress((void**)&wlo,  g_wlo);
    cudaGetSymbolAddress((void**)&qf,   g_qf);   cudaGetSymbolAddress((void**)&kf,   g_kf);
    cudaGetSymbolAddress((void**)&qhi,  g_qhi);  cudaGetSymbolAddress((void**)&qlo,  g_qlo);
    cudaGetSymbolAddress((void**)&khi,  g_khi);  cudaGetSymbolAddress((void**)&klo,  g_klo);
    cudaGetSymbolAddress((void**)&vthi, g_vthi); cudaGetSymbolAddress((void**)&vtlo, g_vtlo);
    cudaGetSymbolAddress((void**)&ahi,  g_ahi);  cudaGetSymbolAddress((void**)&alo,  g_alo);

    const size_t WSZ = (size_t)HID * HID;

    cudaFuncSetAttribute(gemm_mma<0>, cudaFuncAttributeMaxDynamicSharedMemorySize, SMEM_SZ);
    cudaFuncSetAttribute(gemm_mma<2>, cudaFuncAttributeMaxDynamicSharedMemorySize, SMEM_SZ);
    cudaFuncSetAttribute(attn_kernel, cudaFuncAttributeMaxDynamicSharedMemorySize, ASMEM);

    // 1. quantize weights -> bf16 hi/lo
    quantize_kernel<<<dim3(GROUPS_PER_W / 8, 4), 256>>>(wq, wk, wv, wo);

    // 2. x -> bf16 hi/lo
    convert_kernel<<<(SEQ * HID / 4) / 256, 256>>>(x, xhi, xlo);

    // 3. projections
    dim3 g16(16, 16, 1);
    gemm_mma<0><<<g16, 256, SMEM_SZ>>>(xhi, xlo, whi,           wlo,           qf, 0, 0,
                                       HID, HID, HID, HID);
    gemm_mma<0><<<g16, 256, SMEM_SZ>>>(xhi, xlo, whi + WSZ,     wlo + WSZ,     kf, 0, 0,
                                       HID, HID, HID, HID);
    gemm_mma<2><<<g16, 256, SMEM_SZ>>>(xhi, xlo, whi + 2 * WSZ, wlo + 2 * WSZ, 0, vthi, vtlo,
                                       HID, HID, HID, SEQ);

    // 4. RoPE -> bf16 hi/lo
    rope_kernel<<<dim3(SEQ * NHEADS * 64 / 256, 2), 256>>>(qf, kf, qhi, qlo, khi, klo);

    // 5. fused flash attention -> ahi/alo
    attn_kernel<<<dim3(16, NHEADS), 256, ASMEM>>>(qhi, qlo, khi, klo, vthi, vtlo, mask, ahi, alo);

    // 6. out = attn @ Wo^T -> d_out
    gemm_mma<0><<<g16, 256, SMEM_SZ>>>(ahi, alo, whi + 3 * WSZ, wlo + 3 * WSZ,
                                       (float*)d_out, 0, 0, HID, HID, HID, HID);
}

// round 12
// speedup vs baseline: 1.6736x; 1.1089x over previous
#include <cuda_runtime.h>
#include <cuda_bf16.h>
#include <stdint.h>
#include <math.h>

#define HID 2048
#define SEQ 2048
#define NHEADS 16
#define HDIM 128
#define GROUPS_PER_W (HID*HID/128)

typedef __nv_bfloat16 bf16;

// ---------------- scratch (static device memory; no allocation) ----------------
__device__ __align__(256) bf16  g_xhi[(size_t)SEQ*HID],  g_xlo[(size_t)SEQ*HID];
__device__ __align__(256) bf16  g_whi[4][(size_t)HID*HID], g_wlo[4][(size_t)HID*HID];
__device__ __align__(256) float g_qf[(size_t)SEQ*HID],  g_kf[(size_t)SEQ*HID];
__device__ __align__(256) bf16  g_qhi[(size_t)SEQ*HID], g_qlo[(size_t)SEQ*HID];
__device__ __align__(256) bf16  g_khi[(size_t)SEQ*HID], g_klo[(size_t)SEQ*HID];
__device__ __align__(256) bf16  g_vthi[(size_t)SEQ*HID], g_vtlo[(size_t)SEQ*HID]; // V^T per head [d][t]
__device__ __align__(256) bf16  g_ahi[(size_t)SEQ*HID], g_alo[(size_t)SEQ*HID];

// ---------------- small helpers ----------------
__device__ __forceinline__ void split(float v, bf16& h, bf16& l) {
    h = __float2bfloat16(v);
    l = __float2bfloat16(v - __bfloat162float(h));
}
__device__ __forceinline__ uint32_t pack2(bf16 a, bf16 b) {
    uint16_t ua = *(uint16_t*)&a, ub = *(uint16_t*)&b;
    return (uint32_t)ua | ((uint32_t)ub << 16);
}
__device__ __forceinline__ uint32_t smem_u32(const void* p) {
    uint32_t a;
    asm("{ .reg .u64 t; cvta.to.shared.u64 t, %1; cvt.u32.u64 %0, t; }" : "=r"(a) : "l"(p));
    return a;
}

// ---------------- warp-mma primitives (baseline PTX, sm_80+) ----------------
__device__ __forceinline__ void ldsm4(uint32_t& r0, uint32_t& r1, uint32_t& r2, uint32_t& r3,
                                      uint32_t addr) {
    asm volatile("ldmatrix.sync.aligned.m8n8.x4.shared.b16 {%0,%1,%2,%3}, [%4];"
                 : "=r"(r0), "=r"(r1), "=r"(r2), "=r"(r3) : "r"(addr));
}
__device__ __forceinline__ void mma16816(float* c, const uint32_t* a, const uint32_t* b) {
    asm volatile(
        "mma.sync.aligned.m16n8k16.row.col.f32.bf16.bf16.f32 "
        "{%0,%1,%2,%3}, {%4,%5,%6,%7}, {%8,%9}, {%0,%1,%2,%3};"
        : "+f"(c[0]), "+f"(c[1]), "+f"(c[2]), "+f"(c[3])
        : "r"(a[0]), "r"(a[1]), "r"(a[2]), "r"(a[3]), "r"(b[0]), "r"(b[1]));
}

// ---------------- quantize: w -> ternary*scale -> bf16 hi/lo ----------------
__global__ void quantize_kernel(const float* __restrict__ w0, const float* __restrict__ w1,
                                const float* __restrict__ w2, const float* __restrict__ w3) {
    const float* srcs[4] = {w0, w1, w2, w3};
    const float* w = srcs[blockIdx.y];
    bf16* ohi = g_whi[blockIdx.y];
    bf16* olo = g_wlo[blockIdx.y];
    int warp = threadIdx.x >> 5, lane = threadIdx.x & 31;
    size_t g = (size_t)blockIdx.x * 8 + warp;
    float4 v = *(const float4*)(w + g * 128 + lane * 4);
    float s = fabsf(v.x) + fabsf(v.y) + fabsf(v.z) + fabsf(v.w);
    #pragma unroll
    for (int o = 16; o; o >>= 1) s += __shfl_xor_sync(0xffffffffu, s, o);
    float scale = fmaxf(s * (1.f / 128.f), 1e-8f);
    float q[4];
    float wn;
    wn = v.x / scale; q[0] = (wn > 0.5f ? scale : (wn < -0.5f ? -scale : 0.f));
    wn = v.y / scale; q[1] = (wn > 0.5f ? scale : (wn < -0.5f ? -scale : 0.f));
    wn = v.z / scale; q[2] = (wn > 0.5f ? scale : (wn < -0.5f ? -scale : 0.f));
    wn = v.w / scale; q[3] = (wn > 0.5f ? scale : (wn < -0.5f ? -scale : 0.f));
    bf16 h[4], l[4];
    #pragma unroll
    for (int i = 0; i < 4; i++) split(q[i], h[i], l[i]);
    *(uint2*)(ohi + g * 128 + lane * 4) = make_uint2(pack2(h[0], h[1]), pack2(h[2], h[3]));
    *(uint2*)(olo + g * 128 + lane * 4) = make_uint2(pack2(l[0], l[1]), pack2(l[2], l[3]));
}

// ---------------- fp32 -> bf16 hi/lo converter (for x) ----------------
__global__ void convert_kernel(const float* __restrict__ src, bf16* __restrict__ hi,
                               bf16* __restrict__ lo) {
    int i = blockIdx.x * 256 + threadIdx.x;
    float4 v = ((const float4*)src)[i];
    bf16 h0,l0,h1,l1,h2,l2,h3,l3;
    split(v.x,h0,l0); split(v.y,h1,l1); split(v.z,h2,l2); split(v.w,h3,l3);
    ((uint2*)hi)[i] = make_uint2(pack2(h0,h1), pack2(h2,h3));
    ((uint2*)lo)[i] = make_uint2(pack2(l0,l1), pack2(l2,l3));
}

// ---------------- RoPE: fp32 q/k -> roped bf16 hi/lo ----------------
__global__ void rope_kernel(const float* __restrict__ qf, const float* __restrict__ kf,
                            bf16* __restrict__ qhi, bf16* __restrict__ qlo,
                            bf16* __restrict__ khi, bf16* __restrict__ klo) {
    int idx = blockIdx.x * blockDim.x + threadIdx.x;
    const float* y = (blockIdx.y == 0) ? qf : kf;
    bf16* oh = (blockIdx.y == 0) ? qhi : khi;
    bf16* ol = (blockIdx.y == 0) ? qlo : klo;
    int j = idx & 63;
    int h = (idx >> 6) & 15;
    int s = idx >> 10;
    float inv = (float)(1.0 / pow(10000.0, (double)j / 64.0));
    float f = (float)s * inv;
    double fd = (double)f;
    float c  = (float)cos(fd);
    float sn = (float)sin(fd);
    size_t p = (size_t)s * HID + h * HDIM + j;
    float x1 = y[p], x2 = y[p + 64];
    float o1 = x1 * c - x2 * sn;
    float o2 = x1 * sn + x2 * c;
    bf16 hh, ll;
    split(o1, hh, ll); oh[p] = hh;      ol[p] = ll;
    split(o2, hh, ll); oh[p + 64] = hh; ol[p + 64] = ll;
}

// ---------------- warp-mma GEMM (round-9 engine): C = (Ahi+Alo)(Bhi+Blo)^T ----------------
// OUT: 0 = fp32 C, 2 = bf16 hi/lo split TRANSPOSED C (via smem transpose).
#define KC 32
#define ROWB 80
#define TILEB (128*ROWB)
#define BUFB  (4*TILEB)
#define SMEM_SZ (2*BUFB)

template<int OUT>
__global__ void __launch_bounds__(256, 1)
gemm_mma(const bf16* __restrict__ Ahi, const bf16* __restrict__ Alo,
         const bf16* __restrict__ Bhi, const bf16* __restrict__ Blo,
         float* __restrict__ Cf, bf16* __restrict__ Chi, bf16* __restrict__ Clo,
         int K, int lda, int ldb, int ldc)
{
    int bx = blockIdx.x, by = blockIdx.y;

    extern __shared__ char smem[];
    uint32_t sb = smem_u32(smem);

    int tid = threadIdx.x;
    int lane = tid & 31, wid = tid >> 5;
    int wm = wid & 1;
    int wn = wid >> 1;

    int NC = K >> 5;

    const bf16* const srcs[4] = {Ahi, Alo, Bhi, Blo};
    const int ldsv[4] = {lda, lda, ldb, ldb};
    const int r0v[4]  = {by*128, by*128, bx*128, bx*128};
    int row0 = tid >> 2, seg = tid & 3;

    uint4 stg[8];
    auto ldg = [&](int c) {
        int k0 = c * KC;
        #pragma unroll
        for (int tl = 0; tl < 4; tl++) {
            const bf16* s = srcs[tl]; int ld = ldsv[tl]; int r0 = r0v[tl];
            stg[tl*2+0] = *(const uint4*)(s + (long long)(r0 + row0)      * ld + k0 + seg*8);
            stg[tl*2+1] = *(const uint4*)(s + (long long)(r0 + row0 + 64) * ld + k0 + seg*8);
        }
    };
    auto sts = [&](int buf) {
        char* bp = smem + buf * BUFB;
        #pragma unroll
        for (int tl = 0; tl < 4; tl++) {
            *(uint4*)(bp + tl*TILEB + row0*ROWB + seg*16)        = stg[tl*2+0];
            *(uint4*)(bp + tl*TILEB + (row0+64)*ROWB + seg*16)   = stg[tl*2+1];
        }
    };

    float acc[4][4][4];
    #pragma unroll
    for (int i = 0; i < 4; i++)
        #pragma unroll
        for (int j = 0; j < 4; j++)
            #pragma unroll
            for (int r = 0; r < 4; r++) acc[i][j][r] = 0.f;

    ldg(0); sts(0); __syncthreads();

    uint32_t arow = wm*64 + (lane & 7) + ((lane >> 3) & 1) * 8;
    uint32_t brow = wn*32 + (lane & 7) + ((lane >> 3) & 1) * 8;
    uint32_t kcol = ((lane >> 4) & 1) * 16;

    for (int c = 0; c < NC; c++) {
        int cb = c & 1, nb = (c + 1) & 1;
        bool pf = (c + 1 < NC);
        if (pf) ldg(c + 1);

        uint32_t base = sb + cb * BUFB;
        #pragma unroll
        for (int ks = 0; ks < 2; ks++) {
            uint32_t af[2][4][4];
            uint32_t bfr[2][4][2];
            #pragma unroll
            for (int mt = 0; mt < 4; mt++) {
                uint32_t ra = base + (arow + mt*16) * ROWB + ks*32 + kcol;
                ldsm4(af[0][mt][0], af[0][mt][1], af[0][mt][2], af[0][mt][3], ra);
                ldsm4(af[1][mt][0], af[1][mt][1], af[1][mt][2], af[1][mt][3], ra + TILEB);
            }
            #pragma unroll
            for (int np = 0; np < 2; np++) {
                uint32_t rb = base + 2*TILEB + (brow + np*16) * ROWB + ks*32 + kcol;
                uint32_t r0, r1, r2, r3;
                ldsm4(r0, r1, r2, r3, rb);
                bfr[0][np*2][0] = r0;   bfr[0][np*2][1]   = r2;
                bfr[0][np*2+1][0] = r1; bfr[0][np*2+1][1] = r3;
                ldsm4(r0, r1, r2, r3, rb + TILEB);
                bfr[1][np*2][0] = r0;   bfr[1][np*2][1]   = r2;
                bfr[1][np*2+1][0] = r1; bfr[1][np*2+1][1] = r3;
            }
            #pragma unroll
            for (int mt = 0; mt < 4; mt++)
                #pragma unroll
                for (int nt = 0; nt < 4; nt++) {
                    mma16816(acc[mt][nt], af[0][mt], bfr[0][nt]);
                    mma16816(acc[mt][nt], af[0][mt], bfr[1][nt]);
                    mma16816(acc[mt][nt], af[1][mt], bfr[0][nt]);
                }
        }
        __syncthreads();
        if (pf) { sts(nb); __syncthreads(); }
    }

    int tg = lane >> 2, t4 = lane & 3;
    if (OUT == 2) {
        // transpose via smem, then coalesced stores (verified in round 10)
        const int TP = 136;
        bf16* tbuf = (bf16*)smem;
        #pragma unroll
        for (int pass = 0; pass < 2; pass++) {
            #pragma unroll
            for (int mt = 0; mt < 4; mt++)
                #pragma unroll
                for (int rp = 0; rp < 2; rp++) {
                    int ml = wm*64 + mt*16 + tg + rp*8;
                    #pragma unroll
                    for (int nt = 0; nt < 4; nt++) {
                        int cl = wn*32 + nt*8 + t4*2;
                        float c0 = acc[mt][nt][rp*2+0], c1 = acc[mt][nt][rp*2+1];
                        bf16 h0, l0, h1, l1;
                        split(c0, h0, l0); split(c1, h1, l1);
                        tbuf[(cl+0)*TP + ml] = pass ? l0 : h0;
                        tbuf[(cl+1)*TP + ml] = pass ? l1 : h1;
                    }
                }
            __syncthreads();
            {
                int row = tid >> 1, part = tid & 1;
                bf16* dst = (pass ? Clo : Chi) + (long long)(bx*128 + row) * ldc + by*128 + part*64;
                const uint4* s4 = (const uint4*)(tbuf + row*TP + part*64);
                uint4* d4 = (uint4*)dst;
                #pragma unroll
                for (int j = 0; j < 8; j++) d4[j] = s4[j];
            }
            __syncthreads();
        }
        return;
    }
    #pragma unroll
    for (int mt = 0; mt < 4; mt++)
        #pragma unroll
        for (int rp = 0; rp < 2; rp++) {
            int m = by*128 + wm*64 + mt*16 + tg + rp*8;
            #pragma unroll
            for (int nt = 0; nt < 4; nt++) {
                int col = bx*128 + wn*32 + nt*8 + t4*2;
                *(float2*)(Cf + (long long)m * ldc + col)
                    = make_float2(acc[mt][nt][rp*2+0], acc[mt][nt][rp*2+1]);
            }
        }
}

// ---------------- fused flash attention, key blocks of 64 ----------------
// 1D grid 256 CTAs (big qb first), 256 threads, warp w owns q rows w*16..+15.
#define AQ    0
#define AQLO  34816
#define AKHI  69632
#define AKLO  87040
#define AVHI  104448
#define AVLO  122880
#define AMSK  141312
#define ASMEM 141824

__global__ void __launch_bounds__(256, 1)
attn_kernel(const bf16* __restrict__ qhi, const bf16* __restrict__ qlo,
            const bf16* __restrict__ khi, const bf16* __restrict__ klo,
            const bf16* __restrict__ vthi, const bf16* __restrict__ vtlo,
            const int* __restrict__ mask,
            bf16* __restrict__ ahi, bf16* __restrict__ alo)
{
    int bid = blockIdx.x;
    int h  = bid & 15;
    int qb = 15 - (bid >> 4);            // big CTAs first (LPT)
    extern __shared__ char smem[];
    uint32_t sb = smem_u32(smem);
    int tid = threadIdx.x, lane = tid & 31, wid = tid >> 5;
    int tg = lane >> 2, t4 = lane & 3;

    // resident Q tiles (hi & lo): 128 rows x 128 cols, stride 272B
    {
        int r = tid >> 1, cb = (tid & 1) * 64;
        const uint4* s0 = (const uint4*)(qhi + (size_t)(qb*128 + r)*HID + h*128 + cb);
        const uint4* s1 = (const uint4*)(qlo + (size_t)(qb*128 + r)*HID + h*128 + cb);
        uint4* d0 = (uint4*)(smem + AQ   + r*272 + cb*2);
        uint4* d1 = (uint4*)(smem + AQLO + r*272 + cb*2);
        #pragma unroll
        for (int j = 0; j < 8; j++) { d0[j] = s0[j]; d1[j] = s1[j]; }
    }

    float o[16][4];
    #pragma unroll
    for (int i = 0; i < 16; i++)
        #pragma unroll
        for (int j = 0; j < 4; j++) o[i][j] = 0.f;
    float m0 = -INFINITY, m1 = -INFINITY, l0 = 0.f, l1 = 0.f;

    uint32_t lrow = (lane & 7) + ((lane >> 3) & 1) * 8;
    uint32_t kcol = ((lane >> 4) & 1) * 16;
    uint32_t arow = sb + AQ + (wid*16 + lrow) * 272 + kcol;
    uint32_t bro272 = lrow * 272 + kcol;
    uint32_t bro144 = lrow * 144 + kcol;
    int rowg0 = qb*128 + wid*16 + tg;     // this thread's rows: rowg0, rowg0+8
    const float SC = 0.088388347648318447f;   // 1/sqrt(128)

    int NTB = 2*qb + 2;
    for (int tb = 0; tb < NTB; tb++) {
        __syncthreads();
        {   // K: 64 rows x 128 cols (stride 272); V^T: 128 rows x 64 cols (stride 144)
            int rk = tid >> 2, ck = (tid & 3) * 32;
            const uint4* s0 = (const uint4*)(khi + (size_t)(tb*64 + rk)*HID + h*128 + ck);
            const uint4* s1 = (const uint4*)(klo + (size_t)(tb*64 + rk)*HID + h*128 + ck);
            uint4* d0 = (uint4*)(smem + AKHI + rk*272 + ck*2);
            uint4* d1 = (uint4*)(smem + AKLO + rk*272 + ck*2);
            int rv = tid >> 1, cv = (tid & 1) * 32;
            const uint4* s2 = (const uint4*)(vthi + (size_t)(h*128 + rv)*SEQ + tb*64 + cv);
            const uint4* s3 = (const uint4*)(vtlo + (size_t)(h*128 + rv)*SEQ + tb*64 + cv);
            uint4* d2 = (uint4*)(smem + AVHI + rv*144 + cv*2);
            uint4* d3 = (uint4*)(smem + AVLO + rv*144 + cv*2);
            #pragma unroll
            for (int j = 0; j < 4; j++) { d0[j] = s0[j]; d1[j] = s1[j]; d2[j] = s2[j]; d3[j] = s3[j]; }
            if (tid < 64) ((int*)(smem + AMSK))[tid] = mask[tb*64 + tid];
        }
        __syncthreads();

        // ---- S = Q K^T (warp: 16 rows x 64 cols) ----
        float s[8][4];
        #pragma unroll
        for (int i = 0; i < 8; i++)
            #pragma unroll
            for (int j = 0; j < 4; j++) s[i][j] = 0.f;

        #pragma unroll
        for (int ks = 0; ks < 8; ks++) {
            uint32_t ah[4], al[4];
            ldsm4(ah[0], ah[1], ah[2], ah[3], arow + ks*32);
            ldsm4(al[0], al[1], al[2], al[3], arow + ks*32 + (AQLO - AQ));
            #pragma unroll
            for (int np = 0; np < 4; np++) {
                uint32_t rb = sb + AKHI + np*16*272 + bro272 + ks*32;
                uint32_t r0, r1, r2, r3;
                ldsm4(r0, r1, r2, r3, rb);
                uint32_t bh0[2] = {r0, r2}, bh1[2] = {r1, r3};
                ldsm4(r0, r1, r2, r3, rb + (AKLO - AKHI));
                uint32_t bl0[2] = {r0, r2}, bl1[2] = {r1, r3};
                mma16816(s[2*np],   ah, bh0); mma16816(s[2*np],   ah, bl0); mma16816(s[2*np],   al, bh0);
                mma16816(s[2*np+1], ah, bh1); mma16816(s[2*np+1], ah, bl1); mma16816(s[2*np+1], al, bh1);
            }
        }

        // ---- scale + causal + pad mask, row max ----
        const int* mk = (const int*)(smem + AMSK);
        float mx0 = -INFINITY, mx1 = -INFINITY;
        #pragma unroll
        for (int nt = 0; nt < 8; nt++) {
            int cl = nt*8 + t4*2;
            int cg = tb*64 + cl;
            bool v0 = (mk[cl] != 0), v1 = (mk[cl+1] != 0);
            s[nt][0] = (v0 && cg     <= rowg0    ) ? s[nt][0]*SC : -INFINITY;
            s[nt][1] = (v1 && cg + 1 <= rowg0    ) ? s[nt][1]*SC : -INFINITY;
            s[nt][2] = (v0 && cg     <= rowg0 + 8) ? s[nt][2]*SC : -INFINITY;
            s[nt][3] = (v1 && cg + 1 <= rowg0 + 8) ? s[nt][3]*SC : -INFINITY;
            mx0 = fmaxf(mx0, fmaxf(s[nt][0], s[nt][1]));
            mx1 = fmaxf(mx1, fmaxf(s[nt][2], s[nt][3]));
        }
        mx0 = fmaxf(mx0, __shfl_xor_sync(0xffffffffu, mx0, 1));
        mx0 = fmaxf(mx0, __shfl_xor_sync(0xffffffffu, mx0, 2));
        mx1 = fmaxf(mx1, __shfl_xor_sync(0xffffffffu, mx1, 1));
        mx1 = fmaxf(mx1, __shfl_xor_sync(0xffffffffu, mx1, 2));

        float mn0 = fmaxf(m0, mx0), mn1 = fmaxf(m1, mx1);
        float base0 = (mn0 == -INFINITY) ? 0.f : mn0;
        float base1 = (mn1 == -INFINITY) ? 0.f : mn1;
        float f0 = __expf(m0 - base0);
        float f1 = __expf(m1 - base1);
        m0 = mn0; m1 = mn1;

        float sum0 = 0.f, sum1 = 0.f;
        #pragma unroll
        for (int nt = 0; nt < 8; nt++) {
            s[nt][0] = __expf(s[nt][0] - base0);
            s[nt][1] = __expf(s[nt][1] - base0);
            s[nt][2] = __expf(s[nt][2] - base1);
            s[nt][3] = __expf(s[nt][3] - base1);
            sum0 += s[nt][0] + s[nt][1];
            sum1 += s[nt][2] + s[nt][3];
        }
        sum0 += __shfl_xor_sync(0xffffffffu, sum0, 1);
        sum0 += __shfl_xor_sync(0xffffffffu, sum0, 2);
        sum1 += __shfl_xor_sync(0xffffffffu, sum1, 1);
        sum1 += __shfl_xor_sync(0xffffffffu, sum1, 2);
        l0 = l0 * f0 + sum0;
        l1 = l1 * f1 + sum1;

        #pragma unroll
        for (int dn = 0; dn < 16; dn++) {
            o[dn][0] *= f0; o[dn][1] *= f0;
            o[dn][2] *= f1; o[dn][3] *= f1;
        }

        // ---- O += P V  (P from registers: C fragment == A fragment layout) ----
        #pragma unroll
        for (int ks = 0; ks < 4; ks++) {
            uint32_t aph[4], apl[4];
            {
                bf16 hh[8], ll[8];
                split(s[2*ks][0], hh[0], ll[0]); split(s[2*ks][1], hh[1], ll[1]);
                split(s[2*ks][2], hh[2], ll[2]); split(s[2*ks][3], hh[3], ll[3]);
                split(s[2*ks+1][0], hh[4], ll[4]); split(s[2*ks+1][1], hh[5], ll[5]);
                split(s[2*ks+1][2], hh[6], ll[6]); split(s[2*ks+1][3], hh[7], ll[7]);
                aph[0] = pack2(hh[0], hh[1]); aph[1] = pack2(hh[2], hh[3]);
                aph[2] = pack2(hh[4], hh[5]); aph[3] = pack2(hh[6], hh[7]);
                apl[0] = pack2(ll[0], ll[1]); apl[1] = pack2(ll[2], ll[3]);
                apl[2] = pack2(ll[4], ll[5]); apl[3] = pack2(ll[6], ll[7]);
            }
            #pragma unroll
            for (int np = 0; np < 8; np++) {
                uint32_t rb = sb + AVHI + np*16*144 + bro144 + ks*32;
                uint32_t r0, r1, r2, r3;
                ldsm4(r0, r1, r2, r3, rb);
                uint32_t vh0[2] = {r0, r2}, vh1[2] = {r1, r3};
                ldsm4(r0, r1, r2, r3, rb + (AVLO - AVHI));
                uint32_t vl0[2] = {r0, r2}, vl1[2] = {r1, r3};
                mma16816(o[2*np],   aph, vh0); mma16816(o[2*np],   aph, vl0); mma16816(o[2*np],   apl, vh0);
                mma16816(o[2*np+1], aph, vh1); mma16816(o[2*np+1], aph, vl1); mma16816(o[2*np+1], apl, vh1);
            }
        }
    }

    // ---- epilogue: O /= l, split to ahi/alo [s, h*128+d] ----
    float i0 = 1.f / l0, i1 = 1.f / l1;
    int mrow = qb*128 + wid*16 + tg;
    #pragma unroll
    for (int dn = 0; dn < 16; dn++) {
        int col = h*128 + dn*8 + t4*2;
        bf16 h0, q0, h1, q1;
        split(o[dn][0]*i0, h0, q0); split(o[dn][1]*i0, h1, q1);
        *(uint32_t*)(ahi + (size_t)mrow*HID + col) = pack2(h0, h1);
        *(uint32_t*)(alo + (size_t)mrow*HID + col) = pack2(q0, q1);
        split(o[dn][2]*i1, h0, q0); split(o[dn][3]*i1, h1, q1);
        *(uint32_t*)(ahi + (size_t)(mrow+8)*HID + col) = pack2(h0, h1);
        *(uint32_t*)(alo + (size_t)(mrow+8)*HID + col) = pack2(q0, q1);
    }
}

// ---------------- launch ----------------
extern "C" void kernel_launch(void* const* d_in, const int* in_sizes, int n_in,
                              void* d_out, int out_size) {
    const float* x    = (const float*)d_in[0];
    const int*   mask = (const int*)d_in[1];
    const float* wq   = (const float*)d_in[2];
    const float* wk   = (const float*)d_in[3];
    const float* wv   = (const float*)d_in[4];
    const float* wo   = (const float*)d_in[5];

    bf16 *xhi, *xlo, *whi, *wlo, *qhi, *qlo, *khi, *klo, *vthi, *vtlo, *ahi, *alo;
    float *qf, *kf;
    cudaGetSymbolAddress((void**)&xhi,  g_xhi);  cudaGetSymbolAddress((void**)&xlo,  g_xlo);
    cudaGetSymbolAddress((void**)&whi,  g_whi);  cudaGetSymbolAddress((void**)&wlo,  g_wlo);
    cudaGetSymbolAddress((void**)&qf,   g_qf);   cudaGetSymbolAddress((void**)&kf,   g_kf);
    cudaGetSymbolAddress((void**)&qhi,  g_qhi);  cudaGetSymbolAddress((void**)&qlo,  g_qlo);
    cudaGetSymbolAddress((void**)&khi,  g_khi);  cudaGetSymbolAddress((void**)&klo,  g_klo);
    cudaGetSymbolAddress((void**)&vthi, g_vthi); cudaGetSymbolAddress((void**)&vtlo, g_vtlo);
    cudaGetSymbolAddress((void**)&ahi,  g_ahi);  cudaGetSymbolAddress((void**)&alo,  g_alo);

    const size_t WSZ = (size_t)HID * HID;

    cudaFuncSetAttribute(gemm_mma<0>, cudaFuncAttributeMaxDynamicSharedMemorySize, SMEM_SZ);
    cudaFuncSetAttribute(gemm_mma<2>, cudaFuncAttributeMaxDynamicSharedMemorySize, SMEM_SZ);
    cudaFuncSetAttribute(attn_kernel, cudaFuncAttributeMaxDynamicSharedMemorySize, ASMEM);

    // 1. quantize weights -> bf16 hi/lo
    quantize_kernel<<<dim3(GROUPS_PER_W / 8, 4), 256>>>(wq, wk, wv, wo);

    // 2. x -> bf16 hi/lo
    convert_kernel<<<(SEQ * HID / 4) / 256, 256>>>(x, xhi, xlo);

    // 3. projections
    dim3 g16(16, 16, 1);
    gemm_mma<0><<<g16, 256, SMEM_SZ>>>(xhi, xlo, whi,           wlo,           qf, 0, 0,
                                       HID, HID, HID, HID);
    gemm_mma<0><<<g16, 256, SMEM_SZ>>>(xhi, xlo, whi + WSZ,     wlo + WSZ,     kf, 0, 0,
                                       HID, HID, HID, HID);
    gemm_mma<2><<<g16, 256, SMEM_SZ>>>(xhi, xlo, whi + 2 * WSZ, wlo + 2 * WSZ, 0, vthi, vtlo,
                                       HID, HID, HID, SEQ);

    // 4. RoPE -> bf16 hi/lo
    rope_kernel<<<dim3(SEQ * NHEADS * 64 / 256, 2), 256>>>(qf, kf, qhi, qlo, khi, klo);

    // 5. fused flash attention -> ahi/alo
    attn_kernel<<<256, 256, ASMEM>>>(qhi, qlo, khi, klo, vthi, vtlo, mask, ahi, alo);

    // 6. out = attn @ Wo^T -> d_out
    gemm_mma<0><<<g16, 256, SMEM_SZ>>>(ahi, alo, whi + 3 * WSZ, wlo + 3 * WSZ,
                                       (float*)d_out, 0, 0, HID, HID, HID, HID);
}

// round 13
// speedup vs baseline: 1.6910x; 1.0104x over previous
#include <cuda_runtime.h>
#include <cuda_bf16.h>
#include <stdint.h>
#include <math.h>

#define HID 2048
#define SEQ 2048
#define NHEADS 16
#define HDIM 128
#define GROUPS_PER_W (HID*HID/128)

typedef __nv_bfloat16 bf16;

// ---------------- scratch (static device memory; no allocation) ----------------
__device__ __align__(256) bf16  g_xhi[(size_t)SEQ*HID],  g_xlo[(size_t)SEQ*HID];
__device__ __align__(256) bf16  g_whi[4][(size_t)HID*HID], g_wlo[4][(size_t)HID*HID];
__device__ __align__(256) float g_qf[(size_t)SEQ*HID],  g_kf[(size_t)SEQ*HID];
__device__ __align__(256) bf16  g_qhi[(size_t)SEQ*HID], g_qlo[(size_t)SEQ*HID];
__device__ __align__(256) bf16  g_khi[(size_t)SEQ*HID], g_klo[(size_t)SEQ*HID];
__device__ __align__(256) bf16  g_vthi[(size_t)SEQ*HID], g_vtlo[(size_t)SEQ*HID]; // V^T per head [d][t]
__device__ __align__(256) bf16  g_ahi[(size_t)SEQ*HID], g_alo[(size_t)SEQ*HID];
__device__ int g_mflag[32];   // per-64-key-block "mask all ones" flag

// ---------------- small helpers ----------------
__device__ __forceinline__ void split(float v, bf16& h, bf16& l) {
    h = __float2bfloat16(v);
    l = __float2bfloat16(v - __bfloat162float(h));
}
__device__ __forceinline__ uint32_t pack2(bf16 a, bf16 b) {
    uint16_t ua = *(uint16_t*)&a, ub = *(uint16_t*)&b;
    return (uint32_t)ua | ((uint32_t)ub << 16);
}
__device__ __forceinline__ uint32_t smem_u32(const void* p) {
    uint32_t a;
    asm("{ .reg .u64 t; cvta.to.shared.u64 t, %1; cvt.u32.u64 %0, t; }" : "=r"(a) : "l"(p));
    return a;
}

// ---------------- warp-mma + cp.async primitives (baseline PTX, sm_80+) ----------------
__device__ __forceinline__ void ldsm4(uint32_t& r0, uint32_t& r1, uint32_t& r2, uint32_t& r3,
                                      uint32_t addr) {
    asm volatile("ldmatrix.sync.aligned.m8n8.x4.shared.b16 {%0,%1,%2,%3}, [%4];"
                 : "=r"(r0), "=r"(r1), "=r"(r2), "=r"(r3) : "r"(addr));
}
__device__ __forceinline__ void mma16816(float* c, const uint32_t* a, const uint32_t* b) {
    asm volatile(
        "mma.sync.aligned.m16n8k16.row.col.f32.bf16.bf16.f32 "
        "{%0,%1,%2,%3}, {%4,%5,%6,%7}, {%8,%9}, {%0,%1,%2,%3};"
        : "+f"(c[0]), "+f"(c[1]), "+f"(c[2]), "+f"(c[3])
        : "r"(a[0]), "r"(a[1]), "r"(a[2]), "r"(a[3]), "r"(b[0]), "r"(b[1]));
}
__device__ __forceinline__ void cpa16(uint32_t dst, const void* src) {
    asm volatile("cp.async.cg.shared.global [%0], [%1], 16;" :: "r"(dst), "l"(src));
}
#define CP_COMMIT() asm volatile("cp.async.commit_group;" ::: "memory")
#define CP_WAIT(n)  asm volatile("cp.async.wait_group %0;" :: "n"(n) : "memory")

// ---------------- quantize: w -> ternary*scale -> bf16 hi/lo ----------------
__global__ void quantize_kernel(const float* __restrict__ w0, const float* __restrict__ w1,
                                const float* __restrict__ w2, const float* __restrict__ w3) {
    const float* srcs[4] = {w0, w1, w2, w3};
    const float* w = srcs[blockIdx.y];
    bf16* ohi = g_whi[blockIdx.y];
    bf16* olo = g_wlo[blockIdx.y];
    int warp = threadIdx.x >> 5, lane = threadIdx.x & 31;
    size_t g = (size_t)blockIdx.x * 8 + warp;
    float4 v = *(const float4*)(w + g * 128 + lane * 4);
    float s = fabsf(v.x) + fabsf(v.y) + fabsf(v.z) + fabsf(v.w);
    #pragma unroll
    for (int o = 16; o; o >>= 1) s += __shfl_xor_sync(0xffffffffu, s, o);
    float scale = fmaxf(s * (1.f / 128.f), 1e-8f);
    float q[4];
    float wn;
    wn = v.x / scale; q[0] = (wn > 0.5f ? scale : (wn < -0.5f ? -scale : 0.f));
    wn = v.y / scale; q[1] = (wn > 0.5f ? scale : (wn < -0.5f ? -scale : 0.f));
    wn = v.z / scale; q[2] = (wn > 0.5f ? scale : (wn < -0.5f ? -scale : 0.f));
    wn = v.w / scale; q[3] = (wn > 0.5f ? scale : (wn < -0.5f ? -scale : 0.f));
    bf16 h[4], l[4];
    #pragma unroll
    for (int i = 0; i < 4; i++) split(q[i], h[i], l[i]);
    *(uint2*)(ohi + g * 128 + lane * 4) = make_uint2(pack2(h[0], h[1]), pack2(h[2], h[3]));
    *(uint2*)(olo + g * 128 + lane * 4) = make_uint2(pack2(l[0], l[1]), pack2(l[2], l[3]));
}

// ---------------- fp32 -> bf16 hi/lo converter (for x) ----------------
__global__ void convert_kernel(const float* __restrict__ src, bf16* __restrict__ hi,
                               bf16* __restrict__ lo) {
    int i = blockIdx.x * 256 + threadIdx.x;
    float4 v = ((const float4*)src)[i];
    bf16 h0,l0,h1,l1,h2,l2,h3,l3;
    split(v.x,h0,l0); split(v.y,h1,l1); split(v.z,h2,l2); split(v.w,h3,l3);
    ((uint2*)hi)[i] = make_uint2(pack2(h0,h1), pack2(h2,h3));
    ((uint2*)lo)[i] = make_uint2(pack2(l0,l1), pack2(l2,l3));
}

// ---------------- per-64-block mask flags ----------------
__global__ void maskflag_kernel(const int* __restrict__ mask) {
    int t = threadIdx.x;
    if (t < 32) {
        int f = 1;
        for (int i = 0; i < 64; i++) f &= (mask[t * 64 + i] != 0);
        g_mflag[t] = f;
    }
}

// ---------------- RoPE: fp32 q/k -> roped bf16 hi/lo (Q pre-scaled by 1/sqrt(d)) ----------------
__global__ void rope_kernel(const float* __restrict__ qf, const float* __restrict__ kf,
                            bf16* __restrict__ qhi, bf16* __restrict__ qlo,
                            bf16* __restrict__ khi, bf16* __restrict__ klo) {
    int idx = blockIdx.x * blockDim.x + threadIdx.x;
    const float* y = (blockIdx.y == 0) ? qf : kf;
    bf16* oh = (blockIdx.y == 0) ? qhi : khi;
    bf16* ol = (blockIdx.y == 0) ? qlo : klo;
    float post = (blockIdx.y == 0) ? 0.088388347648318447f : 1.f;   // fold 1/sqrt(128) into Q
    int j = idx & 63;
    int h = (idx >> 6) & 15;
    int s = idx >> 10;
    float inv = (float)(1.0 / pow(10000.0, (double)j / 64.0));
    float f = (float)s * inv;
    double fd = (double)f;
    float c  = (float)cos(fd);
    float sn = (float)sin(fd);
    size_t p = (size_t)s * HID + h * HDIM + j;
    float x1 = y[p], x2 = y[p + 64];
    float o1 = (x1 * c - x2 * sn) * post;
    float o2 = (x1 * sn + x2 * c) * post;
    bf16 hh, ll;
    split(o1, hh, ll); oh[p] = hh;      ol[p] = ll;
    split(o2, hh, ll); oh[p + 64] = hh; ol[p + 64] = ll;
}

// ---------------- warp-mma GEMM (round-9 engine): C = (Ahi+Alo)(Bhi+Blo)^T ----------------
// OUT: 0 = fp32 C, 2 = bf16 hi/lo split TRANSPOSED C (via smem transpose).
#define KC 32
#define ROWB 80
#define TILEB (128*ROWB)
#define BUFB  (4*TILEB)
#define SMEM_SZ (2*BUFB)

template<int OUT>
__global__ void __launch_bounds__(256, 1)
gemm_mma(const bf16* __restrict__ Ahi, const bf16* __restrict__ Alo,
         const bf16* __restrict__ Bhi, const bf16* __restrict__ Blo,
         float* __restrict__ Cf, bf16* __restrict__ Chi, bf16* __restrict__ Clo,
         int K, int lda, int ldb, int ldc)
{
    int bx = blockIdx.x, by = blockIdx.y;

    extern __shared__ char smem[];
    uint32_t sb = smem_u32(smem);

    int tid = threadIdx.x;
    int lane = tid & 31, wid = tid >> 5;
    int wm = wid & 1;
    int wn = wid >> 1;

    int NC = K >> 5;

    const bf16* const srcs[4] = {Ahi, Alo, Bhi, Blo};
    const int ldsv[4] = {lda, lda, ldb, ldb};
    const int r0v[4]  = {by*128, by*128, bx*128, bx*128};
    int row0 = tid >> 2, seg = tid & 3;

    uint4 stg[8];
    auto ldg = [&](int c) {
        int k0 = c * KC;
        #pragma unroll
        for (int tl = 0; tl < 4; tl++) {
            const bf16* s = srcs[tl]; int ld = ldsv[tl]; int r0 = r0v[tl];
            stg[tl*2+0] = *(const uint4*)(s + (long long)(r0 + row0)      * ld + k0 + seg*8);
            stg[tl*2+1] = *(const uint4*)(s + (long long)(r0 + row0 + 64) * ld + k0 + seg*8);
        }
    };
    auto sts = [&](int buf) {
        char* bp = smem + buf * BUFB;
        #pragma unroll
        for (int tl = 0; tl < 4; tl++) {
            *(uint4*)(bp + tl*TILEB + row0*ROWB + seg*16)        = stg[tl*2+0];
            *(uint4*)(bp + tl*TILEB + (row0+64)*ROWB + seg*16)   = stg[tl*2+1];
        }
    };

    float acc[4][4][4];
    #pragma unroll
    for (int i = 0; i < 4; i++)
        #pragma unroll
        for (int j = 0; j < 4; j++)
            #pragma unroll
            for (int r = 0; r < 4; r++) acc[i][j][r] = 0.f;

    ldg(0); sts(0); __syncthreads();

    uint32_t arow = wm*64 + (lane & 7) + ((lane >> 3) & 1) * 8;
    uint32_t brow = wn*32 + (lane & 7) + ((lane >> 3) & 1) * 8;
    uint32_t kcol = ((lane >> 4) & 1) * 16;

    for (int c = 0; c < NC; c++) {
        int cb = c & 1, nb = (c + 1) & 1;
        bool pf = (c + 1 < NC);
        if (pf) ldg(c + 1);

        uint32_t base = sb + cb * BUFB;
        #pragma unroll
        for (int ks = 0; ks < 2; ks++) {
            uint32_t af[2][4][4];
            uint32_t bfr[2][4][2];
            #pragma unroll
            for (int mt = 0; mt < 4; mt++) {
                uint32_t ra = base + (arow + mt*16) * ROWB + ks*32 + kcol;
                ldsm4(af[0][mt][0], af[0][mt][1], af[0][mt][2], af[0][mt][3], ra);
                ldsm4(af[1][mt][0], af[1][mt][1], af[1][mt][2], af[1][mt][3], ra + TILEB);
            }
            #pragma unroll
            for (int np = 0; np < 2; np++) {
                uint32_t rb = base + 2*TILEB + (brow + np*16) * ROWB + ks*32 + kcol;
                uint32_t r0, r1, r2, r3;
                ldsm4(r0, r1, r2, r3, rb);
                bfr[0][np*2][0] = r0;   bfr[0][np*2][1]   = r2;
                bfr[0][np*2+1][0] = r1; bfr[0][np*2+1][1] = r3;
                ldsm4(r0, r1, r2, r3, rb + TILEB);
                bfr[1][np*2][0] = r0;   bfr[1][np*2][1]   = r2;
                bfr[1][np*2+1][0] = r1; bfr[1][np*2+1][1] = r3;
            }
            #pragma unroll
            for (int mt = 0; mt < 4; mt++)
                #pragma unroll
                for (int nt = 0; nt < 4; nt++) {
                    mma16816(acc[mt][nt], af[0][mt], bfr[0][nt]);
                    mma16816(acc[mt][nt], af[0][mt], bfr[1][nt]);
                    mma16816(acc[mt][nt], af[1][mt], bfr[0][nt]);
                }
        }
        __syncthreads();
        if (pf) { sts(nb); __syncthreads(); }
    }

    int tg = lane >> 2, t4 = lane & 3;
    if (OUT == 2) {
        // transpose via smem, then coalesced stores (verified in round 10)
        const int TP = 136;
        bf16* tbuf = (bf16*)smem;
        #pragma unroll
        for (int pass = 0; pass < 2; pass++) {
            #pragma unroll
            for (int mt = 0; mt < 4; mt++)
                #pragma unroll
                for (int rp = 0; rp < 2; rp++) {
                    int ml = wm*64 + mt*16 + tg + rp*8;
                    #pragma unroll
                    for (int nt = 0; nt < 4; nt++) {
                        int cl = wn*32 + nt*8 + t4*2;
                        float c0 = acc[mt][nt][rp*2+0], c1 = acc[mt][nt][rp*2+1];
                        bf16 h0, l0, h1, l1;
                        split(c0, h0, l0); split(c1, h1, l1);
                        tbuf[(cl+0)*TP + ml] = pass ? l0 : h0;
                        tbuf[(cl+1)*TP + ml] = pass ? l1 : h1;
                    }
                }
            __syncthreads();
            {
                int row = tid >> 1, part = tid & 1;
                bf16* dst = (pass ? Clo : Chi) + (long long)(bx*128 + row) * ldc + by*128 + part*64;
                const uint4* s4 = (const uint4*)(tbuf + row*TP + part*64);
                uint4* d4 = (uint4*)dst;
                #pragma unroll
                for (int j = 0; j < 8; j++) d4[j] = s4[j];
            }
            __syncthreads();
        }
        return;
    }
    #pragma unroll
    for (int mt = 0; mt < 4; mt++)
        #pragma unroll
        for (int rp = 0; rp < 2; rp++) {
            int m = by*128 + wm*64 + mt*16 + tg + rp*8;
            #pragma unroll
            for (int nt = 0; nt < 4; nt++) {
                int col = bx*128 + wn*32 + nt*8 + t4*2;
                *(float2*)(Cf + (long long)m * ldc + col)
                    = make_float2(acc[mt][nt][rp*2+0], acc[mt][nt][rp*2+1]);
            }
        }
}

// ---------------- fused flash attention, key blocks of 64, cp.async double buffer ----------------
// 1D grid 256 CTAs (big qb first), 256 threads, warp w owns q rows w*16..+15.
// SMEM: Q hi/lo resident (69632B) + 2 K/V buffers (71680B each) = 212992B.
#define AQ     0
#define AQLO   34816
#define ABUF   69632
#define OBK_LO 17408         // Klo within buffer
#define OBV_HI 34816         // Vhi within buffer
#define OBV_LO 53248         // Vlo within buffer
#define BUFSZ  71680
#define ASMEM  (ABUF + 2*BUFSZ)

__global__ void __launch_bounds__(256, 1)
attn_kernel(const bf16* __restrict__ qhi, const bf16* __restrict__ qlo,
            const bf16* __restrict__ khi, const bf16* __restrict__ klo,
            const bf16* __restrict__ vthi, const bf16* __restrict__ vtlo,
            const int* __restrict__ mask, const int* __restrict__ mflag,
            bf16* __restrict__ ahi, bf16* __restrict__ alo)
{
    int bid = blockIdx.x;
    int h  = bid & 15;
    int qb = 15 - (bid >> 4);            // big CTAs first (LPT)
    extern __shared__ char smem[];
    uint32_t sb = smem_u32(smem);
    int tid = threadIdx.x, lane = tid & 31, wid = tid >> 5;
    int tg = lane >> 2, t4 = lane & 3;

    // resident Q tiles (hi & lo): 128 rows x 128 cols, stride 272B
    {
        int r = tid >> 1, cb = (tid & 1) * 64;
        const uint4* s0 = (const uint4*)(qhi + (size_t)(qb*128 + r)*HID + h*128 + cb);
        const uint4* s1 = (const uint4*)(qlo + (size_t)(qb*128 + r)*HID + h*128 + cb);
        uint4* d0 = (uint4*)(smem + AQ   + r*272 + cb*2);
        uint4* d1 = (uint4*)(smem + AQLO + r*272 + cb*2);
        #pragma unroll
        for (int j = 0; j < 8; j++) { d0[j] = s0[j]; d1[j] = s1[j]; }
    }

    // async K/V loader: K 64x128 (stride 272), V^T 128x64 (stride 144)
    int rk = tid >> 2, ck = (tid & 3) * 32;
    int rv = tid >> 1, cv = (tid & 1) * 32;
    auto issue = [&](int tb, int buf) {
        uint32_t bp = sb + ABUF + buf * BUFSZ;
        const bf16* sk0 = khi  + (size_t)(tb*64 + rk)*HID + h*128 + ck;
        const bf16* sk1 = klo  + (size_t)(tb*64 + rk)*HID + h*128 + ck;
        uint32_t dk = bp + rk*272 + ck*2;
        #pragma unroll
        for (int j = 0; j < 4; j++) {
            cpa16(dk + j*16,          sk0 + j*8);
            cpa16(dk + OBK_LO + j*16, sk1 + j*8);
        }
        const bf16* sv0 = vthi + (size_t)(h*128 + rv)*SEQ + tb*64 + cv;
        const bf16* sv1 = vtlo + (size_t)(h*128 + rv)*SEQ + tb*64 + cv;
        uint32_t dv = bp + OBV_HI + rv*144 + cv*2;
        #pragma unroll
        for (int j = 0; j < 4; j++) {
            cpa16(dv + j*16,                   sv0 + j*8);
            cpa16(dv + (OBV_LO-OBV_HI) + j*16, sv1 + j*8);
        }
    };

    float o[16][4];
    #pragma unroll
    for (int i = 0; i < 16; i++)
        #pragma unroll
        for (int j = 0; j < 4; j++) o[i][j] = 0.f;
    float m0 = -INFINITY, m1 = -INFINITY, l0 = 0.f, l1 = 0.f;

    uint32_t lrow = (lane & 7) + ((lane >> 3) & 1) * 8;
    uint32_t kcol = ((lane >> 4) & 1) * 16;
    uint32_t arow = sb + AQ + (wid*16 + lrow) * 272 + kcol;
    uint32_t bro272 = lrow * 272 + kcol;
    uint32_t bro144 = lrow * 144 + kcol;
    int rowg0 = qb*128 + wid*16 + tg;     // this thread's rows: rowg0, rowg0+8
    int wrow0 = qb*128 + wid*16;          // warp's min row

    int NTB = 2*qb + 2;
    issue(0, 0); CP_COMMIT();

    for (int tb = 0; tb < NTB; tb++) {
        if (tb + 1 < NTB) issue(tb + 1, (tb + 1) & 1);
        CP_COMMIT();
        CP_WAIT(1);                       // block tb landed
        __syncthreads();

        uint32_t kb = sb + ABUF + (tb & 1) * BUFSZ;

        // ---- S = Q K^T (warp: 16 rows x 64 cols); Q pre-scaled by 1/sqrt(d) ----
        float s[8][4];
        #pragma unroll
        for (int i = 0; i < 8; i++)
            #pragma unroll
            for (int j = 0; j < 4; j++) s[i][j] = 0.f;

        #pragma unroll
        for (int ks = 0; ks < 8; ks++) {
            uint32_t ah[4], al[4];
            ldsm4(ah[0], ah[1], ah[2], ah[3], arow + ks*32);
            ldsm4(al[0], al[1], al[2], al[3], arow + ks*32 + (AQLO - AQ));
            #pragma unroll
            for (int np = 0; np < 4; np++) {
                uint32_t rb = kb + np*16*272 + bro272 + ks*32;
                uint32_t r0, r1, r2, r3;
                ldsm4(r0, r1, r2, r3, rb);
                uint32_t bh0[2] = {r0, r2}, bh1[2] = {r1, r3};
                ldsm4(r0, r1, r2, r3, rb + OBK_LO);
                uint32_t bl0[2] = {r0, r2}, bl1[2] = {r1, r3};
                mma16816(s[2*np],   ah, bh0); mma16816(s[2*np],   ah, bl0); mma16816(s[2*np],   al, bh0);
                mma16816(s[2*np+1], ah, bh1); mma16816(s[2*np+1], ah, bl1); mma16816(s[2*np+1], al, bh1);
            }
        }

        // ---- masking (fast path for fully-visible unmasked blocks), row max ----
        float mx0 = -INFINITY, mx1 = -INFINITY;
        bool full = (tb*64 + 63 <= wrow0) && (__ldg(&mflag[tb]) != 0);   // warp-uniform
        if (full) {
            #pragma unroll
            for (int nt = 0; nt < 8; nt++) {
                mx0 = fmaxf(mx0, fmaxf(s[nt][0], s[nt][1]));
                mx1 = fmaxf(mx1, fmaxf(s[nt][2], s[nt][3]));
            }
        } else {
            #pragma unroll
            for (int nt = 0; nt < 8; nt++) {
                int cl = nt*8 + t4*2;
                int cg = tb*64 + cl;
                int2 mk = __ldg((const int2*)&mask[cg]);
                bool v0 = (mk.x != 0), v1 = (mk.y != 0);
                s[nt][0] = (v0 && cg     <= rowg0    ) ? s[nt][0] : -INFINITY;
                s[nt][1] = (v1 && cg + 1 <= rowg0    ) ? s[nt][1] : -INFINITY;
                s[nt][2] = (v0 && cg     <= rowg0 + 8) ? s[nt][2] : -INFINITY;
                s[nt][3] = (v1 && cg + 1 <= rowg0 + 8) ? s[nt][3] : -INFINITY;
                mx0 = fmaxf(mx0, fmaxf(s[nt][0], s[nt][1]));
                mx1 = fmaxf(mx1, fmaxf(s[nt][2], s[nt][3]));
            }
        }
        mx0 = fmaxf(mx0, __shfl_xor_sync(0xffffffffu, mx0, 1));
        mx0 = fmaxf(mx0, __shfl_xor_sync(0xffffffffu, mx0, 2));
        mx1 = fmaxf(mx1, __shfl_xor_sync(0xffffffffu, mx1, 1));
        mx1 = fmaxf(mx1, __shfl_xor_sync(0xffffffffu, mx1, 2));

        float mn0 = fmaxf(m0, mx0), mn1 = fmaxf(m1, mx1);
        float base0 = (mn0 == -INFINITY) ? 0.f : mn0;
        float base1 = (mn1 == -INFINITY) ? 0.f : mn1;
        float f0 = __expf(m0 - base0);
        float f1 = __expf(m1 - base1);
        m0 = mn0; m1 = mn1;

        float sum0 = 0.f, sum1 = 0.f;
        #pragma unroll
        for (int nt = 0; nt < 8; nt++) {
            s[nt][0] = __expf(s[nt][0] - base0);
            s[nt][1] = __expf(s[nt][1] - base0);
            s[nt][2] = __expf(s[nt][2] - base1);
            s[nt][3] = __expf(s[nt][3] - base1);
            sum0 += s[nt][0] + s[nt][1];
            sum1 += s[nt][2] + s[nt][3];
        }
        sum0 += __shfl_xor_sync(0xffffffffu, sum0, 1);
        sum0 += __shfl_xor_sync(0xffffffffu, sum0, 2);
        sum1 += __shfl_xor_sync(0xffffffffu, sum1, 1);
        sum1 += __shfl_xor_sync(0xffffffffu, sum1, 2);
        l0 = l0 * f0 + sum0;
        l1 = l1 * f1 + sum1;

        #pragma unroll
        for (int dn = 0; dn < 16; dn++) {
            o[dn][0] *= f0; o[dn][1] *= f0;
            o[dn][2] *= f1; o[dn][3] *= f1;
        }

        // ---- O += P V  (P from registers: C fragment == A fragment layout) ----
        #pragma unroll
        for (int ks = 0; ks < 4; ks++) {
            uint32_t aph[4], apl[4];
            {
                bf16 hh[8], ll[8];
                split(s[2*ks][0], hh[0], ll[0]); split(s[2*ks][1], hh[1], ll[1]);
                split(s[2*ks][2], hh[2], ll[2]); split(s[2*ks][3], hh[3], ll[3]);
                split(s[2*ks+1][0], hh[4], ll[4]); split(s[2*ks+1][1], hh[5], ll[5]);
                split(s[2*ks+1][2], hh[6], ll[6]); split(s[2*ks+1][3], hh[7], ll[7]);
                aph[0] = pack2(hh[0], hh[1]); aph[1] = pack2(hh[2], hh[3]);
                aph[2] = pack2(hh[4], hh[5]); aph[3] = pack2(hh[6], hh[7]);
                apl[0] = pack2(ll[0], ll[1]); apl[1] = pack2(ll[2], ll[3]);
                apl[2] = pack2(ll[4], ll[5]); apl[3] = pack2(ll[6], ll[7]);
            }
            #pragma unroll
            for (int np = 0; np < 8; np++) {
                uint32_t rb = kb + OBV_HI + np*16*144 + bro144 + ks*32;
                uint32_t r0, r1, r2, r3;
                ldsm4(r0, r1, r2, r3, rb);
                uint32_t vh0[2] = {r0, r2}, vh1[2] = {r1, r3};
                ldsm4(r0, r1, r2, r3, rb + (OBV_LO - OBV_HI));
                uint32_t vl0[2] = {r0, r2}, vl1[2] = {r1, r3};
                mma16816(o[2*np],   aph, vh0); mma16816(o[2*np],   aph, vl0); mma16816(o[2*np],   apl, vh0);
                mma16816(o[2*np+1], aph, vh1); mma16816(o[2*np+1], aph, vl1); mma16816(o[2*np+1], apl, vh1);
            }
        }
        __syncthreads();   // buffer tb%2 reusable by issue() next iteration
    }

    // ---- epilogue: O /= l, split to ahi/alo [s, h*128+d] ----
    float i0 = 1.f / l0, i1 = 1.f / l1;
    int mrow = qb*128 + wid*16 + tg;
    #pragma unroll
    for (int dn = 0; dn < 16; dn++) {
        int col = h*128 + dn*8 + t4*2;
        bf16 h0, q0, h1, q1;
        split(o[dn][0]*i0, h0, q0); split(o[dn][1]*i0, h1, q1);
        *(uint32_t*)(ahi + (size_t)mrow*HID + col) = pack2(h0, h1);
        *(uint32_t*)(alo + (size_t)mrow*HID + col) = pack2(q0, q1);
        split(o[dn][2]*i1, h0, q0); split(o[dn][3]*i1, h1, q1);
        *(uint32_t*)(ahi + (size_t)(mrow+8)*HID + col) = pack2(h0, h1);
        *(uint32_t*)(alo + (size_t)(mrow+8)*HID + col) = pack2(q0, q1);
    }
}

// ---------------- launch ----------------
extern "C" void kernel_launch(void* const* d_in, const int* in_sizes, int n_in,
                              void* d_out, int out_size) {
    const float* x    = (const float*)d_in[0];
    const int*   mask = (const int*)d_in[1];
    const float* wq   = (const float*)d_in[2];
    const float* wk   = (const float*)d_in[3];
    const float* wv   = (const float*)d_in[4];
    const float* wo   = (const float*)d_in[5];

    bf16 *xhi, *xlo, *whi, *wlo, *qhi, *qlo, *khi, *klo, *vthi, *vtlo, *ahi, *alo;
    float *qf, *kf;
    int* mflag;
    cudaGetSymbolAddress((void**)&xhi,  g_xhi);  cudaGetSymbolAddress((void**)&xlo,  g_xlo);
    cudaGetSymbolAddress((void**)&whi,  g_whi);  cudaGetSymbolAddress((void**)&wlo,  g_wlo);
    cudaGetSymbolAddress((void**)&qf,   g_qf);   cudaGetSymbolAddress((void**)&kf,   g_kf);
    cudaGetSymbolAddress((void**)&qhi,  g_qhi);  cudaGetSymbolAddress((void**)&qlo,  g_qlo);
    cudaGetSymbolAddress((void**)&khi,  g_khi);  cudaGetSymbolAddress((void**)&klo,  g_klo);
    cudaGetSymbolAddress((void**)&vthi, g_vthi); cudaGetSymbolAddress((void**)&vtlo, g_vtlo);
    cudaGetSymbolAddress((void**)&ahi,  g_ahi);  cudaGetSymbolAddress((void**)&alo,  g_alo);
    cudaGetSymbolAddress((void**)&mflag, g_mflag);

    const size_t WSZ = (size_t)HID * HID;

    cudaFuncSetAttribute(gemm_mma<0>, cudaFuncAttributeMaxDynamicSharedMemorySize, SMEM_SZ);
    cudaFuncSetAttribute(gemm_mma<2>, cudaFuncAttributeMaxDynamicSharedMemorySize, SMEM_SZ);
    cudaFuncSetAttribute(attn_kernel, cudaFuncAttributeMaxDynamicSharedMemorySize, ASMEM);

    // 1. quantize weights -> bf16 hi/lo; mask flags
    quantize_kernel<<<dim3(GROUPS_PER_W / 8, 4), 256>>>(wq, wk, wv, wo);
    maskflag_kernel<<<1, 32>>>(mask);

    // 2. x -> bf16 hi/lo
    convert_kernel<<<(SEQ * HID / 4) / 256, 256>>>(x, xhi, xlo);

    // 3. projections
    dim3 g16(16, 16, 1);
    gemm_mma<0><<<g16, 256, SMEM_SZ>>>(xhi, xlo, whi,           wlo,           qf, 0, 0,
                                       HID, HID, HID, HID);
    gemm_mma<0><<<g16, 256, SMEM_SZ>>>(xhi, xlo, whi + WSZ,     wlo + WSZ,     kf, 0, 0,
                                       HID, HID, HID, HID);
    gemm_mma<2><<<g16, 256, SMEM_SZ>>>(xhi, xlo, whi + 2 * WSZ, wlo + 2 * WSZ, 0, vthi, vtlo,
                                       HID, HID, HID, SEQ);

    // 4. RoPE -> bf16 hi/lo (Q pre-scaled by 1/sqrt(d))
    rope_kernel<<<dim3(SEQ * NHEADS * 64 / 256, 2), 256>>>(qf, kf, qhi, qlo, khi, klo);

    // 5. fused flash attention -> ahi/alo
    attn_kernel<<<256, 256, ASMEM>>>(qhi, qlo, khi, klo, vthi, vtlo, mask, mflag, ahi, alo);

    // 6. out = attn @ Wo^T -> d_out
    gemm_mma<0><<<g16, 256, SMEM_SZ>>>(ahi, alo, whi + 3 * WSZ, wlo + 3 * WSZ,
                                       (float*)d_out, 0, 0, HID, HID, HID, HID);
}

// round 15
// speedup vs baseline: 3.0077x; 1.7787x over previous
#include <cuda_runtime.h>
#include <cuda_bf16.h>
#include <stdint.h>
#include <math.h>

#define HID 2048
#define SEQ 2048
#define NHEADS 16
#define HDIM 128
#define GROUPS_PER_W (HID*HID/128)

typedef __nv_bfloat16 bf16;

// ---------------- scratch (static device memory; no allocation) ----------------
__device__ __align__(256) bf16  g_xhi[(size_t)SEQ*HID],  g_xlo[(size_t)SEQ*HID];
__device__ __align__(256) bf16  g_whi[4][(size_t)HID*HID], g_wlo[4][(size_t)HID*HID];
__device__ __align__(256) float g_qf[(size_t)SEQ*HID],  g_kf[(size_t)SEQ*HID];
__device__ __align__(256) bf16  g_qhi[(size_t)SEQ*HID], g_qlo[(size_t)SEQ*HID];
__device__ __align__(256) bf16  g_khi[(size_t)SEQ*HID], g_klo[(size_t)SEQ*HID];
__device__ __align__(256) bf16  g_vthi[(size_t)SEQ*HID], g_vtlo[(size_t)SEQ*HID]; // V^T per head [d][t]
__device__ __align__(256) bf16  g_ahi[(size_t)SEQ*HID], g_alo[(size_t)SEQ*HID];
__device__ __align__(256) float g_ct[(size_t)SEQ*64], g_st[(size_t)SEQ*64];       // RoPE tables
__device__ int g_mflag[32];   // per-64-key-block "mask all ones" flag

// ---------------- small helpers ----------------
__device__ __forceinline__ void split(float v, bf16& h, bf16& l) {
    h = __float2bfloat16(v);
    l = __float2bfloat16(v - __bfloat162float(h));
}
__device__ __forceinline__ uint32_t pack2(bf16 a, bf16 b) {
    uint16_t ua = *(uint16_t*)&a, ub = *(uint16_t*)&b;
    return (uint32_t)ua | ((uint32_t)ub << 16);
}
__device__ __forceinline__ uint32_t smem_u32(const void* p) {
    uint32_t a;
    asm("{ .reg .u64 t; cvta.to.shared.u64 t, %1; cvt.u32.u64 %0, t; }" : "=r"(a) : "l"(p));
    return a;
}

// ---------------- warp-mma + cp.async primitives (baseline PTX, sm_80+) ----------------
__device__ __forceinline__ void ldsm4(uint32_t& r0, uint32_t& r1, uint32_t& r2, uint32_t& r3,
                                      uint32_t addr) {
    asm volatile("ldmatrix.sync.aligned.m8n8.x4.shared.b16 {%0,%1,%2,%3}, [%4];"
                 : "=r"(r0), "=r"(r1), "=r"(r2), "=r"(r3) : "r"(addr));
}
__device__ __forceinline__ void mma16816(float* c, const uint32_t* a, const uint32_t* b) {
    asm volatile(
        "mma.sync.aligned.m16n8k16.row.col.f32.bf16.bf16.f32 "
        "{%0,%1,%2,%3}, {%4,%5,%6,%7}, {%8,%9}, {%0,%1,%2,%3};"
        : "+f"(c[0]), "+f"(c[1]), "+f"(c[2]), "+f"(c[3])
        : "r"(a[0]), "r"(a[1]), "r"(a[2]), "r"(a[3]), "r"(b[0]), "r"(b[1]));
}
__device__ __forceinline__ void cpa16(uint32_t dst, const void* src) {
    asm volatile("cp.async.cg.shared.global [%0], [%1], 16;" :: "r"(dst), "l"(src));
}
#define CP_COMMIT() asm volatile("cp.async.commit_group;" ::: "memory")
#define CP_WAIT(n)  asm volatile("cp.async.wait_group %0;" :: "n"(n) : "memory")

// ---------------- quantize: w -> ternary*scale -> bf16 hi/lo ----------------
__global__ void quantize_kernel(const float* __restrict__ w0, const float* __restrict__ w1,
                                const float* __restrict__ w2, const float* __restrict__ w3) {
    const float* srcs[4] = {w0, w1, w2, w3};
    const float* w = srcs[blockIdx.y];
    bf16* ohi = g_whi[blockIdx.y];
    bf16* olo = g_wlo[blockIdx.y];
    int warp = threadIdx.x >> 5, lane = threadIdx.x & 31;
    size_t g = (size_t)blockIdx.x * 8 + warp;
    float4 v = *(const float4*)(w + g * 128 + lane * 4);
    float s = fabsf(v.x) + fabsf(v.y) + fabsf(v.z) + fabsf(v.w);
    #pragma unroll
    for (int o = 16; o; o >>= 1) s += __shfl_xor_sync(0xffffffffu, s, o);
    float scale = fmaxf(s * (1.f / 128.f), 1e-8f);
    float q[4];
    float wn;
    wn = v.x / scale; q[0] = (wn > 0.5f ? scale : (wn < -0.5f ? -scale : 0.f));
    wn = v.y / scale; q[1] = (wn > 0.5f ? scale : (wn < -0.5f ? -scale : 0.f));
    wn = v.z / scale; q[2] = (wn > 0.5f ? scale : (wn < -0.5f ? -scale : 0.f));
    wn = v.w / scale; q[3] = (wn > 0.5f ? scale : (wn < -0.5f ? -scale : 0.f));
    bf16 h[4], l[4];
    #pragma unroll
    for (int i = 0; i < 4; i++) split(q[i], h[i], l[i]);
    *(uint2*)(ohi + g * 128 + lane * 4) = make_uint2(pack2(h[0], h[1]), pack2(h[2], h[3]));
    *(uint2*)(olo + g * 128 + lane * 4) = make_uint2(pack2(l[0], l[1]), pack2(l[2], l[3]));
}

// ---------------- fp32 -> bf16 hi/lo converter (for x) ----------------
__global__ void convert_kernel(const float* __restrict__ src, bf16* __restrict__ hi,
                               bf16* __restrict__ lo) {
    int i = blockIdx.x * 256 + threadIdx.x;
    float4 v = ((const float4*)src)[i];
    bf16 h0,l0,h1,l1,h2,l2,h3,l3;
    split(v.x,h0,l0); split(v.y,h1,l1); split(v.z,h2,l2); split(v.w,h3,l3);
    ((uint2*)hi)[i] = make_uint2(pack2(h0,h1), pack2(h2,h3));
    ((uint2*)lo)[i] = make_uint2(pack2(l0,l1), pack2(l2,l3));
}

// ---------------- per-64-block mask flags ----------------
__global__ void maskflag_kernel(const int* __restrict__ mask) {
    int t = threadIdx.x;
    if (t < 32) {
        int f = 1;
        for (int i = 0; i < 64; i++) f &= (mask[t * 64 + i] != 0);
        g_mflag[t] = f;
    }
}

// ---------------- RoPE cos/sin tables: 2048 x 64, exact double-precision math ----------------
__global__ void rope_table_kernel() {
    int idx = blockIdx.x * 256 + threadIdx.x;     // s*64 + j
    int j = idx & 63;
    int s = idx >> 6;
    float inv = (float)(1.0 / pow(10000.0, (double)j / 64.0));
    float f = (float)s * inv;                      // fp32-rounded angle (matches ref)
    double fd = (double)f;
    g_ct[idx] = (float)cos(fd);
    g_st[idx] = (float)sin(fd);
}

// ---------------- RoPE: fp32 q/k -> roped bf16 hi/lo (Q pre-scaled by 1/sqrt(d)) ----------------
__global__ void rope_kernel(const float* __restrict__ qf, const float* __restrict__ kf,
                            bf16* __restrict__ qhi, bf16* __restrict__ qlo,
                            bf16* __restrict__ khi, bf16* __restrict__ klo) {
    int idx = blockIdx.x * blockDim.x + threadIdx.x;
    const float* y = (blockIdx.y == 0) ? qf : kf;
    bf16* oh = (blockIdx.y == 0) ? qhi : khi;
    bf16* ol = (blockIdx.y == 0) ? qlo : klo;
    float post = (blockIdx.y == 0) ? 0.088388347648318447f : 1.f;   // fold 1/sqrt(128) into Q
    int j = idx & 63;
    int h = (idx >> 6) & 15;
    int s = idx >> 10;
    float c  = g_ct[s * 64 + j];
    float sn = g_st[s * 64 + j];
    size_t p = (size_t)s * HID + h * HDIM + j;
    float x1 = y[p], x2 = y[p + 64];
    float o1 = (x1 * c - x2 * sn) * post;
    float o2 = (x1 * sn + x2 * c) * post;
    bf16 hh, ll;
    split(o1, hh, ll); oh[p] = hh;      ol[p] = ll;
    split(o2, hh, ll); oh[p + 64] = hh; ol[p + 64] = ll;
}

// ---------------- warp-mma GEMM (round-9 engine): C = (Ahi+Alo)(Bhi+Blo)^T ----------------
// OUT: 0 = fp32 C, 2 = bf16 hi/lo split TRANSPOSED C (via smem transpose).
#define KC 32
#define ROWB 80
#define TILEB (128*ROWB)
#define BUFB  (4*TILEB)
#define SMEM_SZ (2*BUFB)

template<int OUT>
__global__ void __launch_bounds__(256, 1)
gemm_mma(const bf16* __restrict__ Ahi, const bf16* __restrict__ Alo,
         const bf16* __restrict__ Bhi, const bf16* __restrict__ Blo,
         float* __restrict__ Cf, bf16* __restrict__ Chi, bf16* __restrict__ Clo,
         int K, int lda, int ldb, int ldc)
{
    int bx = blockIdx.x, by = blockIdx.y;

    extern __shared__ char smem[];
    uint32_t sb = smem_u32(smem);

    int tid = threadIdx.x;
    int lane = tid & 31, wid = tid >> 5;
    int wm = wid & 1;
    int wn = wid >> 1;

    int NC = K >> 5;

    const bf16* const srcs[4] = {Ahi, Alo, Bhi, Blo};
    const int ldsv[4] = {lda, lda, ldb, ldb};
    const int r0v[4]  = {by*128, by*128, bx*128, bx*128};
    int row0 = tid >> 2, seg = tid & 3;

    uint4 stg[8];
    auto ldg = [&](int c) {
        int k0 = c * KC;
        #pragma unroll
        for (int tl = 0; tl < 4; tl++) {
            const bf16* s = srcs[tl]; int ld = ldsv[tl]; int r0 = r0v[tl];
            stg[tl*2+0] = *(const uint4*)(s + (long long)(r0 + row0)      * ld + k0 + seg*8);
            stg[tl*2+1] = *(const uint4*)(s + (long long)(r0 + row0 + 64) * ld + k0 + seg*8);
        }
    };
    auto sts = [&](int buf) {
        char* bp = smem + buf * BUFB;
        #pragma unroll
        for (int tl = 0; tl < 4; tl++) {
            *(uint4*)(bp + tl*TILEB + row0*ROWB + seg*16)        = stg[tl*2+0];
            *(uint4*)(bp + tl*TILEB + (row0+64)*ROWB + seg*16)   = stg[tl*2+1];
        }
    };

    float acc[4][4][4];
    #pragma unroll
    for (int i = 0; i < 4; i++)
        #pragma unroll
        for (int j = 0; j < 4; j++)
            #pragma unroll
            for (int r = 0; r < 4; r++) acc[i][j][r] = 0.f;

    ldg(0); sts(0); __syncthreads();

    uint32_t arow = wm*64 + (lane & 7) + ((lane >> 3) & 1) * 8;
    uint32_t brow = wn*32 + (lane & 7) + ((lane >> 3) & 1) * 8;
    uint32_t kcol = ((lane >> 4) & 1) * 16;

    for (int c = 0; c < NC; c++) {
        int cb = c & 1, nb = (c + 1) & 1;
        bool pf = (c + 1 < NC);
        if (pf) ldg(c + 1);

        uint32_t base = sb + cb * BUFB;
        #pragma unroll
        for (int ks = 0; ks < 2; ks++) {
            uint32_t af[2][4][4];
            uint32_t bfr[2][4][2];
            #pragma unroll
            for (int mt = 0; mt < 4; mt++) {
                uint32_t ra = base + (arow + mt*16) * ROWB + ks*32 + kcol;
                ldsm4(af[0][mt][0], af[0][mt][1], af[0][mt][2], af[0][mt][3], ra);
                ldsm4(af[1][mt][0], af[1][mt][1], af[1][mt][2], af[1][mt][3], ra + TILEB);
            }
            #pragma unroll
            for (int np = 0; np < 2; np++) {
                uint32_t rb = base + 2*TILEB + (brow + np*16) * ROWB + ks*32 + kcol;
                uint32_t r0, r1, r2, r3;
                ldsm4(r0, r1, r2, r3, rb);
                bfr[0][np*2][0] = r0;   bfr[0][np*2][1]   = r2;
                bfr[0][np*2+1][0] = r1; bfr[0][np*2+1][1] = r3;
                ldsm4(r0, r1, r2, r3, rb + TILEB);
                bfr[1][np*2][0] = r0;   bfr[1][np*2][1]   = r2;
                bfr[1][np*2+1][0] = r1; bfr[1][np*2+1][1] = r3;
            }
            #pragma unroll
            for (int mt = 0; mt < 4; mt++)
                #pragma unroll
                for (int nt = 0; nt < 4; nt++) {
                    mma16816(acc[mt][nt], af[0][mt], bfr[0][nt]);
                    mma16816(acc[mt][nt], af[0][mt], bfr[1][nt]);
                    mma16816(acc[mt][nt], af[1][mt], bfr[0][nt]);
                }
        }
        __syncthreads();
        if (pf) { sts(nb); __syncthreads(); }
    }

    int tg = lane >> 2, t4 = lane & 3;
    if (OUT == 2) {
        // transpose via smem, then coalesced stores (verified in round 10)
        const int TP = 136;
        bf16* tbuf = (bf16*)smem;
        #pragma unroll
        for (int pass = 0; pass < 2; pass++) {
            #pragma unroll
            for (int mt = 0; mt < 4; mt++)
                #pragma unroll
                for (int rp = 0; rp < 2; rp++) {
                    int ml = wm*64 + mt*16 + tg + rp*8;
                    #pragma unroll
                    for (int nt = 0; nt < 4; nt++) {
                        int cl = wn*32 + nt*8 + t4*2;
                        float c0 = acc[mt][nt][rp*2+0], c1 = acc[mt][nt][rp*2+1];
                        bf16 h0, l0, h1, l1;
                        split(c0, h0, l0); split(c1, h1, l1);
                        tbuf[(cl+0)*TP + ml] = pass ? l0 : h0;
                        tbuf[(cl+1)*TP + ml] = pass ? l1 : h1;
                    }
                }
            __syncthreads();
            {
                int row = tid >> 1, part = tid & 1;
                bf16* dst = (pass ? Clo : Chi) + (long long)(bx*128 + row) * ldc + by*128 + part*64;
                const uint4* s4 = (const uint4*)(tbuf + row*TP + part*64);
                uint4* d4 = (uint4*)dst;
                #pragma unroll
                for (int j = 0; j < 8; j++) d4[j] = s4[j];
            }
            __syncthreads();
        }
        return;
    }
    #pragma unroll
    for (int mt = 0; mt < 4; mt++)
        #pragma unroll
        for (int rp = 0; rp < 2; rp++) {
            int m = by*128 + wm*64 + mt*16 + tg + rp*8;
            #pragma unroll
            for (int nt = 0; nt < 4; nt++) {
                int col = bx*128 + wn*32 + nt*8 + t4*2;
                *(float2*)(Cf + (long long)m * ldc + col)
                    = make_float2(acc[mt][nt][rp*2+0], acc[mt][nt][rp*2+1]);
            }
        }
}

// ---------------- fused flash attention, key blocks of 64, cp.async double buffer ----------------
// 1D grid 256 CTAs (big qb first), 256 threads, warp w owns q rows w*16..+15.
#define AQ     0
#define AQLO   34816
#define ABUF   69632
#define OBK_LO 17408         // Klo within buffer
#define OBV_HI 34816         // Vhi within buffer
#define OBV_LO 53248         // Vlo within buffer
#define BUFSZ  71680
#define ASMEM  (ABUF + 2*BUFSZ)

__global__ void __launch_bounds__(256, 1)
attn_kernel(const bf16* __restrict__ qhi, const bf16* __restrict__ qlo,
            const bf16* __restrict__ khi, const bf16* __restrict__ klo,
            const bf16* __restrict__ vthi, const bf16* __restrict__ vtlo,
            const int* __restrict__ mask, const int* __restrict__ mflag,
            bf16* __restrict__ ahi, bf16* __restrict__ alo)
{
    int bid = blockIdx.x;
    int h  = bid & 15;
    int qb = 15 - (bid >> 4);            // big CTAs first (LPT)
    extern __shared__ char smem[];
    uint32_t sb = smem_u32(smem);
    int tid = threadIdx.x, lane = tid & 31, wid = tid >> 5;
    int tg = lane >> 2, t4 = lane & 3;

    // resident Q tiles (hi & lo): 128 rows x 128 cols, stride 272B
    {
        int r = tid >> 1, cb = (tid & 1) * 64;
        const uint4* s0 = (const uint4*)(qhi + (size_t)(qb*128 + r)*HID + h*128 + cb);
        const uint4* s1 = (const uint4*)(qlo + (size_t)(qb*128 + r)*HID + h*128 + cb);
        uint4* d0 = (uint4*)(smem + AQ   + r*272 + cb*2);
        uint4* d1 = (uint4*)(smem + AQLO + r*272 + cb*2);
        #pragma unroll
        for (int j = 0; j < 8; j++) { d0[j] = s0[j]; d1[j] = s1[j]; }
    }

    // async K/V loader: K 64x128 (stride 272), V^T 128x64 (stride 144)
    int rk = tid >> 2, ck = (tid & 3) * 32;
    int rv = tid >> 1, cv = (tid & 1) * 32;
    auto issue = [&](int tb, int buf) {
        uint32_t bp = sb + ABUF + buf * BUFSZ;
        const bf16* sk0 = khi  + (size_t)(tb*64 + rk)*HID + h*128 + ck;
        const bf16* sk1 = klo  + (size_t)(tb*64 + rk)*HID + h*128 + ck;
        uint32_t dk = bp + rk*272 + ck*2;
        #pragma unroll
        for (int j = 0; j < 4; j++) {
            cpa16(dk + j*16,          sk0 + j*8);
            cpa16(dk + OBK_LO + j*16, sk1 + j*8);
        }
        const bf16* sv0 = vthi + (size_t)(h*128 + rv)*SEQ + tb*64 + cv;
        const bf16* sv1 = vtlo + (size_t)(h*128 + rv)*SEQ + tb*64 + cv;
        uint32_t dv = bp + OBV_HI + rv*144 + cv*2;
        #pragma unroll
        for (int j = 0; j < 4; j++) {
            cpa16(dv + j*16,                   sv0 + j*8);
            cpa16(dv + (OBV_LO-OBV_HI) + j*16, sv1 + j*8);
        }
    };

    float o[16][4];
    #pragma unroll
    for (int i = 0; i < 16; i++)
        #pragma unroll
        for (int j = 0; j < 4; j++) o[i][j] = 0.f;
    float m0 = -INFINITY, m1 = -INFINITY, l0 = 0.f, l1 = 0.f;

    uint32_t lrow = (lane & 7) + ((lane >> 3) & 1) * 8;
    uint32_t kcol = ((lane >> 4) & 1) * 16;
    uint32_t arow = sb + AQ + (wid*16 + lrow) * 272 + kcol;
    uint32_t bro272 = lrow * 272 + kcol;
    uint32_t bro144 = lrow * 144 + kcol;
    int rowg0 = qb*128 + wid*16 + tg;     // this thread's rows: rowg0, rowg0+8
    int wrow0 = qb*128 + wid*16;          // warp's min row

    int NTB = 2*qb + 2;
    issue(0, 0); CP_COMMIT();

    for (int tb = 0; tb < NTB; tb++) {
        if (tb + 1 < NTB) issue(tb + 1, (tb + 1) & 1);
        CP_COMMIT();
        CP_WAIT(1);                       // block tb landed
        __syncthreads();

        uint32_t kb = sb + ABUF + (tb & 1) * BUFSZ;

        // ---- S = Q K^T (warp: 16 rows x 64 cols); Q pre-scaled by 1/sqrt(d) ----
        float s[8][4];
        #pragma unroll
        for (int i = 0; i < 8; i++)
            #pragma unroll
            for (int j = 0; j < 4; j++) s[i][j] = 0.f;

        #pragma unroll
        for (int ks = 0; ks < 8; ks++) {
            uint32_t ah[4], al[4];
            ldsm4(ah[0], ah[1], ah[2], ah[3], arow + ks*32);
            ldsm4(al[0], al[1], al[2], al[3], arow + ks*32 + (AQLO - AQ));
            #pragma unroll
            for (int np = 0; np < 4; np++) {
                uint32_t rb = kb + np*16*272 + bro272 + ks*32;
                uint32_t r0, r1, r2, r3;
                ldsm4(r0, r1, r2, r3, rb);
                uint32_t bh0[2] = {r0, r2}, bh1[2] = {r1, r3};
                ldsm4(r0, r1, r2, r3, rb + OBK_LO);
                uint32_t bl0[2] = {r0, r2}, bl1[2] = {r1, r3};
                mma16816(s[2*np],   ah, bh0); mma16816(s[2*np],   ah, bl0); mma16816(s[2*np],   al, bh0);
                mma16816(s[2*np+1], ah, bh1); mma16816(s[2*np+1], ah, bl1); mma16816(s[2*np+1], al, bh1);
            }
        }

        // ---- masking (fast path for fully-visible unmasked blocks), row max ----
        float mx0 = -INFINITY, mx1 = -INFINITY;
        bool full = (tb*64 + 63 <= wrow0) && (__ldg(&mflag[tb]) != 0);   // warp-uniform
        if (full) {
            #pragma unroll
            for (int nt = 0; nt < 8; nt++) {
                mx0 = fmaxf(mx0, fmaxf(s[nt][0], s[nt][1]));
                mx1 = fmaxf(mx1, fmaxf(s[nt][2], s[nt][3]));
            }
        } else {
            #pragma unroll
            for (int nt = 0; nt < 8; nt++) {
                int cl = nt*8 + t4*2;
                int cg = tb*64 + cl;
                int2 mk = __ldg((const int2*)&mask[cg]);
                bool v0 = (mk.x != 0), v1 = (mk.y != 0);
                s[nt][0] = (v0 && cg     <= rowg0    ) ? s[nt][0] : -INFINITY;
                s[nt][1] = (v1 && cg + 1 <= rowg0    ) ? s[nt][1] : -INFINITY;
                s[nt][2] = (v0 && cg     <= rowg0 + 8) ? s[nt][2] : -INFINITY;
                s[nt][3] = (v1 && cg + 1 <= rowg0 + 8) ? s[nt][3] : -INFINITY;
                mx0 = fmaxf(mx0, fmaxf(s[nt][0], s[nt][1]));
                mx1 = fmaxf(mx1, fmaxf(s[nt][2], s[nt][3]));
            }
        }
        mx0 = fmaxf(mx0, __shfl_xor_sync(0xffffffffu, mx0, 1));
        mx0 = fmaxf(mx0, __shfl_xor_sync(0xffffffffu, mx0, 2));
        mx1 = fmaxf(mx1, __shfl_xor_sync(0xffffffffu, mx1, 1));
        mx1 = fmaxf(mx1, __shfl_xor_sync(0xffffffffu, mx1, 2));

        float mn0 = fmaxf(m0, mx0), mn1 = fmaxf(m1, mx1);
        float base0 = (mn0 == -INFINITY) ? 0.f : mn0;
        float base1 = (mn1 == -INFINITY) ? 0.f : mn1;
        float f0 = __expf(m0 - base0);
        float f1 = __expf(m1 - base1);
        m0 = mn0; m1 = mn1;

        float sum0 = 0.f, sum1 = 0.f;
        #pragma unroll
        for (int nt = 0; nt < 8; nt++) {
            s[nt][0] = __expf(s[nt][0] - base0);
            s[nt][1] = __expf(s[nt][1] - base0);
            s[nt][2] = __expf(s[nt][2] - base1);
            s[nt][3] = __expf(s[nt][3] - base1);
            sum0 += s[nt][0] + s[nt][1];
            sum1 += s[nt][2] + s[nt][3];
        }
        sum0 += __shfl_xor_sync(0xffffffffu, sum0, 1);
        sum0 += __shfl_xor_sync(0xffffffffu, sum0, 2);
        sum1 += __shfl_xor_sync(0xffffffffu, sum1, 1);
        sum1 += __shfl_xor_sync(0xffffffffu, sum1, 2);
        l0 = l0 * f0 + sum0;
        l1 = l1 * f1 + sum1;

        #pragma unroll
        for (int dn = 0; dn < 16; dn++) {
            o[dn][0] *= f0; o[dn][1] *= f0;
            o[dn][2] *= f1; o[dn][3] *= f1;
        }

        // ---- O += P V  (P from registers: C fragment == A fragment layout) ----
        #pragma unroll
        for (int ks = 0; ks < 4; ks++) {
            uint32_t aph[4], apl[4];
            {
                bf16 hh[8], ll[8];
                split(s[2*ks][0], hh[0], ll[0]); split(s[2*ks][1], hh[1], ll[1]);
                split(s[2*ks][2], hh[2], ll[2]); split(s[2*ks][3], hh[3], ll[3]);
                split(s[2*ks+1][0], hh[4], ll[4]); split(s[2*ks+1][1], hh[5], ll[5]);
                split(s[2*ks+1][2], hh[6], ll[6]); split(s[2*ks+1][3], hh[7], ll[7]);
                aph[0] = pack2(hh[0], hh[1]); aph[1] = pack2(hh[2], hh[3]);
                aph[2] = pack2(hh[4], hh[5]); aph[3] = pack2(hh[6], hh[7]);
                apl[0] = pack2(ll[0], ll[1]); apl[1] = pack2(ll[2], ll[3]);
                apl[2] = pack2(ll[4], ll[5]); apl[3] = pack2(ll[6], ll[7]);
            }
            #pragma unroll
            for (int np = 0; np < 8; np++) {
                uint32_t rb = kb + OBV_HI + np*16*144 + bro144 + ks*32;
                uint32_t r0, r1, r2, r3;
                ldsm4(r0, r1, r2, r3, rb);
                uint32_t vh0[2] = {r0, r2}, vh1[2] = {r1, r3};
                ldsm4(r0, r1, r2, r3, rb + (OBV_LO - OBV_HI));
                uint32_t vl0[2] = {r0, r2}, vl1[2] = {r1, r3};
                mma16816(o[2*np],   aph, vh0); mma16816(o[2*np],   aph, vl0); mma16816(o[2*np],   apl, vh0);
                mma16816(o[2*np+1], aph, vh1); mma16816(o[2*np+1], aph, vl1); mma16816(o[2*np+1], apl, vh1);
            }
        }
        __syncthreads();   // buffer tb%2 reusable by issue() next iteration
    }

    // ---- epilogue: O /= l, split to ahi/alo [s, h*128+d] ----
    float i0 = 1.f / l0, i1 = 1.f / l1;
    int mrow = qb*128 + wid*16 + tg;
    #pragma unroll
    for (int dn = 0; dn < 16; dn++) {
        int col = h*128 + dn*8 + t4*2;
        bf16 h0, q0, h1, q1;
        split(o[dn][0]*i0, h0, q0); split(o[dn][1]*i0, h1, q1);
        *(uint32_t*)(ahi + (size_t)mrow*HID + col) = pack2(h0, h1);
        *(uint32_t*)(alo + (size_t)mrow*HID + col) = pack2(q0, q1);
        split(o[dn][2]*i1, h0, q0); split(o[dn][3]*i1, h1, q1);
        *(uint32_t*)(ahi + (size_t)(mrow+8)*HID + col) = pack2(h0, h1);
        *(uint32_t*)(alo + (size_t)(mrow+8)*HID + col) = pack2(q0, q1);
    }
}

// ---------------- launch ----------------
extern "C" void kernel_launch(void* const* d_in, const int* in_sizes, int n_in,
                              void* d_out, int out_size) {
    const float* x    = (const float*)d_in[0];
    const int*   mask = (const int*)d_in[1];
    const float* wq   = (const float*)d_in[2];
    const float* wk   = (const float*)d_in[3];
    const float* wv   = (const float*)d_in[4];
    const float* wo   = (const float*)d_in[5];

    bf16 *xhi, *xlo, *whi, *wlo, *qhi, *qlo, *khi, *klo, *vthi, *vtlo, *ahi, *alo;
    float *qf, *kf;
    int* mflag;
    cudaGetSymbolAddress((void**)&xhi,  g_xhi);  cudaGetSymbolAddress((void**)&xlo,  g_xlo);
    cudaGetSymbolAddress((void**)&whi,  g_whi);  cudaGetSymbolAddress((void**)&wlo,  g_wlo);
    cudaGetSymbolAddress((void**)&qf,   g_qf);   cudaGetSymbolAddress((void**)&kf,   g_kf);
    cudaGetSymbolAddress((void**)&qhi,  g_qhi);  cudaGetSymbolAddress((void**)&qlo,  g_qlo);
    cudaGetSymbolAddress((void**)&khi,  g_khi);  cudaGetSymbolAddress((void**)&klo,  g_klo);
    cudaGetSymbolAddress((void**)&vthi, g_vthi); cudaGetSymbolAddress((void**)&vtlo, g_vtlo);
    cudaGetSymbolAddress((void**)&ahi,  g_ahi);  cudaGetSymbolAddress((void**)&alo,  g_alo);
    cudaGetSymbolAddress((void**)&mflag, g_mflag);

    const size_t WSZ = (size_t)HID * HID;

    cudaFuncSetAttribute(gemm_mma<0>, cudaFuncAttributeMaxDynamicSharedMemorySize, SMEM_SZ);
    cudaFuncSetAttribute(gemm_mma<2>, cudaFuncAttributeMaxDynamicSharedMemorySize, SMEM_SZ);
    cudaFuncSetAttribute(attn_kernel, cudaFuncAttributeMaxDynamicSharedMemorySize, ASMEM);

    // 1. quantize weights -> bf16 hi/lo; mask flags; RoPE tables
    quantize_kernel<<<dim3(GROUPS_PER_W / 8, 4), 256>>>(wq, wk, wv, wo);
    maskflag_kernel<<<1, 32>>>(mask);
    rope_table_kernel<<<SEQ * 64 / 256, 256>>>();

    // 2. x -> bf16 hi/lo
    convert_kernel<<<(SEQ * HID / 4) / 256, 256>>>(x, xhi, xlo);

    // 3. projections
    dim3 g16(16, 16, 1);
    gemm_mma<0><<<g16, 256, SMEM_SZ>>>(xhi, xlo, whi,           wlo,           qf, 0, 0,
                                       HID, HID, HID, HID);
    gemm_mma<0><<<g16, 256, SMEM_SZ>>>(xhi, xlo, whi + WSZ,     wlo + WSZ,     kf, 0, 0,
                                       HID, HID, HID, HID);
    gemm_mma<2><<<g16, 256, SMEM_SZ>>>(xhi, xlo, whi + 2 * WSZ, wlo + 2 * WSZ, 0, vthi, vtlo,
                                       HID, HID, HID, SEQ);

    // 4. RoPE -> bf16 hi/lo (Q pre-scaled by 1/sqrt(d)), table-driven
    rope_kernel<<<dim3(SEQ * NHEADS * 64 / 256, 2), 256>>>(qf, kf, qhi, qlo, khi, klo);

    // 5. fused flash attention -> ahi/alo
    attn_kernel<<<256, 256, ASMEM>>>(qhi, qlo, khi, klo, vthi, vtlo, mask, mflag, ahi, alo);

    // 6. out = attn @ Wo^T -> d_out
    gemm_mma<0><<<g16, 256, SMEM_SZ>>>(ahi, alo, whi + 3 * WSZ, wlo + 3 * WSZ,
                                       (float*)d_out, 0, 0, HID, HID, HID, HID);
}

// round 17
// speedup vs baseline: 3.5624x; 1.1844x over previous
#include <cuda_runtime.h>
#include <cuda_bf16.h>
#include <stdint.h>
#include <math.h>

#define HID 2048
#define SEQ 2048
#define NHEADS 16
#define HDIM 128
#define GROUPS_PER_W (HID*HID/128)

typedef __nv_bfloat16 bf16;

// ---------------- scratch (static device memory; no allocation) ----------------
__device__ __align__(256) bf16  g_xhi[(size_t)SEQ*HID],  g_xlo[(size_t)SEQ*HID];
__device__ __align__(256) bf16  g_whi[4][(size_t)HID*HID], g_wlo[4][(size_t)HID*HID];
__device__ __align__(256) float g_qf[(size_t)SEQ*HID],  g_kf[(size_t)SEQ*HID];
__device__ __align__(256) bf16  g_qhi[(size_t)SEQ*HID], g_qlo[(size_t)SEQ*HID];
__device__ __align__(256) bf16  g_khi[(size_t)SEQ*HID], g_klo[(size_t)SEQ*HID];
__device__ __align__(256) bf16  g_vthi[(size_t)SEQ*HID], g_vtlo[(size_t)SEQ*HID]; // V^T per head [d][t]
__device__ __align__(256) bf16  g_ahi[(size_t)SEQ*HID], g_alo[(size_t)SEQ*HID];
__device__ __align__(256) float g_ct[(size_t)SEQ*64], g_st[(size_t)SEQ*64];       // RoPE tables
__device__ int g_mflag[32];   // per-64-key-block "mask all ones" flag

// ---------------- small helpers ----------------
__device__ __forceinline__ void split(float v, bf16& h, bf16& l) {
    h = __float2bfloat16(v);
    l = __float2bfloat16(v - __bfloat162float(h));
}
__device__ __forceinline__ uint32_t pack2(bf16 a, bf16 b) {
    uint16_t ua = *(uint16_t*)&a, ub = *(uint16_t*)&b;
    return (uint32_t)ua | ((uint32_t)ub << 16);
}
__device__ __forceinline__ uint32_t smem_u32(const void* p) {
    uint32_t a;
    asm("{ .reg .u64 t; cvta.to.shared.u64 t, %1; cvt.u32.u64 %0, t; }" : "=r"(a) : "l"(p));
    return a;
}

// ---------------- warp-mma + cp.async primitives (baseline PTX, sm_80+) ----------------
__device__ __forceinline__ void ldsm4(uint32_t& r0, uint32_t& r1, uint32_t& r2, uint32_t& r3,
                                      uint32_t addr) {
    asm volatile("ldmatrix.sync.aligned.m8n8.x4.shared.b16 {%0,%1,%2,%3}, [%4];"
                 : "=r"(r0), "=r"(r1), "=r"(r2), "=r"(r3) : "r"(addr));
}
__device__ __forceinline__ void mma16816(float* c, const uint32_t* a, const uint32_t* b) {
    asm volatile(
        "mma.sync.aligned.m16n8k16.row.col.f32.bf16.bf16.f32 "
        "{%0,%1,%2,%3}, {%4,%5,%6,%7}, {%8,%9}, {%0,%1,%2,%3};"
        : "+f"(c[0]), "+f"(c[1]), "+f"(c[2]), "+f"(c[3])
        : "r"(a[0]), "r"(a[1]), "r"(a[2]), "r"(a[3]), "r"(b[0]), "r"(b[1]));
}
__device__ __forceinline__ void cpa16(uint32_t dst, const void* src) {
    asm volatile("cp.async.cg.shared.global [%0], [%1], 16;" :: "r"(dst), "l"(src));
}
#define CP_COMMIT() asm volatile("cp.async.commit_group;" ::: "memory")
#define CP_WAIT(n)  asm volatile("cp.async.wait_group %0;" :: "n"(n) : "memory")

// ---------------- quantize: w -> ternary*scale -> bf16 hi/lo (division-free) ----------------
__global__ void quantize_kernel(const float* __restrict__ w0, const float* __restrict__ w1,
                                const float* __restrict__ w2, const float* __restrict__ w3) {
    const float* srcs[4] = {w0, w1, w2, w3};
    const float* w = srcs[blockIdx.y];
    bf16* ohi = g_whi[blockIdx.y];
    bf16* olo = g_wlo[blockIdx.y];
    int warp = threadIdx.x >> 5, lane = threadIdx.x & 31;
    size_t g = (size_t)blockIdx.x * 8 + warp;
    float4 v = *(const float4*)(w + g * 128 + lane * 4);
    float s = fabsf(v.x) + fabsf(v.y) + fabsf(v.z) + fabsf(v.w);
    #pragma unroll
    for (int o = 16; o; o >>= 1) s += __shfl_xor_sync(0xffffffffu, s, o);
    float scale = fmaxf(s * (1.f / 128.f), 1e-8f);
    float half_s = 0.5f * scale;
    // |w/scale| > 0.5  <=>  |w| > 0.5*scale   (scale > 0)
    float q[4];
    q[0] = (fabsf(v.x) > half_s) ? copysignf(scale, v.x) : 0.f;
    q[1] = (fabsf(v.y) > half_s) ? copysignf(scale, v.y) : 0.f;
    q[2] = (fabsf(v.z) > half_s) ? copysignf(scale, v.z) : 0.f;
    q[3] = (fabsf(v.w) > half_s) ? copysignf(scale, v.w) : 0.f;
    bf16 h[4], l[4];
    #pragma unroll
    for (int i = 0; i < 4; i++) split(q[i], h[i], l[i]);
    *(uint2*)(ohi + g * 128 + lane * 4) = make_uint2(pack2(h[0], h[1]), pack2(h[2], h[3]));
    *(uint2*)(olo + g * 128 + lane * 4) = make_uint2(pack2(l[0], l[1]), pack2(l[2], l[3]));
}

// ---------------- fp32 -> bf16 hi/lo converter (for x) ----------------
__global__ void convert_kernel(const float* __restrict__ src, bf16* __restrict__ hi,
                               bf16* __restrict__ lo) {
    int i = blockIdx.x * 256 + threadIdx.x;
    float4 v = ((const float4*)src)[i];
    bf16 h0,l0,h1,l1,h2,l2,h3,l3;
    split(v.x,h0,l0); split(v.y,h1,l1); split(v.z,h2,l2); split(v.w,h3,l3);
    ((uint2*)hi)[i] = make_uint2(pack2(h0,h1), pack2(h2,h3));
    ((uint2*)lo)[i] = make_uint2(pack2(l0,l1), pack2(l2,l3));
}

// ---------------- per-64-block mask flags ----------------
__global__ void maskflag_kernel(const int* __restrict__ mask) {
    int t = threadIdx.x;
    if (t < 32) {
        int f = 1;
        for (int i = 0; i < 64; i++) f &= (mask[t * 64 + i] != 0);
        g_mflag[t] = f;
    }
}

// ---------------- RoPE cos/sin tables: 2048 x 64, exact double-precision math ----------------
__global__ void rope_table_kernel() {
    int idx = blockIdx.x * 256 + threadIdx.x;     // s*64 + j
    int j = idx & 63;
    int s = idx >> 6;
    float inv = (float)(1.0 / pow(10000.0, (double)j / 64.0));
    float f = (float)s * inv;                      // fp32-rounded angle (matches ref)
    double fd = (double)f;
    g_ct[idx] = (float)cos(fd);
    g_st[idx] = (float)sin(fd);
}

// ---------------- RoPE: fp32 q/k -> roped bf16 hi/lo (Q pre-scaled by 1/sqrt(d)) ----------------
__global__ void rope_kernel(const float* __restrict__ qf, const float* __restrict__ kf,
                            bf16* __restrict__ qhi, bf16* __restrict__ qlo,
                            bf16* __restrict__ khi, bf16* __restrict__ klo) {
    int idx = blockIdx.x * blockDim.x + threadIdx.x;
    const float* y = (blockIdx.y == 0) ? qf : kf;
    bf16* oh = (blockIdx.y == 0) ? qhi : khi;
    bf16* ol = (blockIdx.y == 0) ? qlo : klo;
    float post = (blockIdx.y == 0) ? 0.088388347648318447f : 1.f;   // fold 1/sqrt(128) into Q
    int j = idx & 63;
    int h = (idx >> 6) & 15;
    int s = idx >> 10;
    float c  = g_ct[s * 64 + j];
    float sn = g_st[s * 64 + j];
    size_t p = (size_t)s * HID + h * HDIM + j;
    float x1 = y[p], x2 = y[p + 64];
    float o1 = (x1 * c - x2 * sn) * post;
    float o2 = (x1 * sn + x2 * c) * post;
    bf16 hh, ll;
    split(o1, hh, ll); oh[p] = hh;      ol[p] = ll;
    split(o2, hh, ll); oh[p + 64] = hh; ol[p + 64] = ll;
}

// ---------------- warp-mma GEMM, 512 threads / 16 warps: C = (Ahi+Alo)(Bhi+Blo)^T ----------------
// 128x128 CTA tile, warp tile 32x32 (4x4 warp grid), K-chunk 32, double-buffered.
// OUT: 0 = fp32 C, 2 = bf16 hi/lo split TRANSPOSED C (via smem transpose).
#define KC 32
#define ROWB 80
#define TILEB (128*ROWB)
#define BUFB  (4*TILEB)
#define SMEM_SZ (2*BUFB)

template<int OUT>
__global__ void __launch_bounds__(512, 1)
gemm_mma(const bf16* __restrict__ Ahi, const bf16* __restrict__ Alo,
         const bf16* __restrict__ Bhi, const bf16* __restrict__ Blo,
         float* __restrict__ Cf, bf16* __restrict__ Chi, bf16* __restrict__ Clo,
         int K, int lda, int ldb, int ldc)
{
    int bx = blockIdx.x, by = blockIdx.y;

    extern __shared__ char smem[];
    uint32_t sb = smem_u32(smem);

    int tid = threadIdx.x;
    int lane = tid & 31, wid = tid >> 5;
    int wm = wid & 3;            // 4 M groups of 32
    int wn = wid >> 2;           // 4 N groups of 32

    int NC = K >> 5;

    const bf16* const srcs[4] = {Ahi, Alo, Bhi, Blo};
    const int ldsv[4] = {lda, lda, ldb, ldb};
    const int r0v[4]  = {by*128, by*128, bx*128, bx*128};
    int row0 = tid >> 2, seg = tid & 3;          // 512 threads: 1 uint4 per tile each

    uint4 stg[4];
    auto ldg = [&](int c) {
        int k0 = c * KC;
        #pragma unroll
        for (int tl = 0; tl < 4; tl++) {
            const bf16* s = srcs[tl]; int ld = ldsv[tl]; int r0 = r0v[tl];
            stg[tl] = *(const uint4*)(s + (long long)(r0 + row0) * ld + k0 + seg*8);
        }
    };
    auto sts = [&](int buf) {
        char* bp = smem + buf * BUFB;
        #pragma unroll
        for (int tl = 0; tl < 4; tl++)
            *(uint4*)(bp + tl*TILEB + row0*ROWB + seg*16) = stg[tl];
    };

    float acc[2][4][4];
    #pragma unroll
    for (int i = 0; i < 2; i++)
        #pragma unroll
        for (int j = 0; j < 4; j++)
            #pragma unroll
            for (int r = 0; r < 4; r++) acc[i][j][r] = 0.f;

    ldg(0); sts(0); __syncthreads();

    uint32_t arow = wm*32 + (lane & 7) + ((lane >> 3) & 1) * 8;   // + mt*16
    uint32_t brow = wn*32 + (lane & 7) + ((lane >> 3) & 1) * 8;   // + np*16
    uint32_t kcol = ((lane >> 4) & 1) * 16;

    for (int c = 0; c < NC; c++) {
        int cb = c & 1, nb = (c + 1) & 1;
        bool pf = (c + 1 < NC);
        if (pf) ldg(c + 1);

        uint32_t base = sb + cb * BUFB;
        #pragma unroll
        for (int ks = 0; ks < 2; ks++) {
            uint32_t af[2][2][4];
            uint32_t bfr[2][4][2];
            #pragma unroll
            for (int mt = 0; mt < 2; mt++) {
                uint32_t ra = base + (arow + mt*16) * ROWB + ks*32 + kcol;
                ldsm4(af[0][mt][0], af[0][mt][1], af[0][mt][2], af[0][mt][3], ra);
                ldsm4(af[1][mt][0], af[1][mt][1], af[1][mt][2], af[1][mt][3], ra + TILEB);
            }
            #pragma unroll
            for (int np = 0; np < 2; np++) {
                uint32_t rb = base + 2*TILEB + (brow + np*16) * ROWB + ks*32 + kcol;
                uint32_t r0, r1, r2, r3;
                ldsm4(r0, r1, r2, r3, rb);
                bfr[0][np*2][0] = r0;   bfr[0][np*2][1]   = r2;
                bfr[0][np*2+1][0] = r1; bfr[0][np*2+1][1] = r3;
                ldsm4(r0, r1, r2, r3, rb + TILEB);
                bfr[1][np*2][0] = r0;   bfr[1][np*2][1]   = r2;
                bfr[1][np*2+1][0] = r1; bfr[1][np*2+1][1] = r3;
            }
            #pragma unroll
            for (int mt = 0; mt < 2; mt++)
                #pragma unroll
                for (int nt = 0; nt < 4; nt++) {
                    mma16816(acc[mt][nt], af[0][mt], bfr[0][nt]);
                    mma16816(acc[mt][nt], af[0][mt], bfr[1][nt]);
                    mma16816(acc[mt][nt], af[1][mt], bfr[0][nt]);
                }
        }
        __syncthreads();
        if (pf) { sts(nb); __syncthreads(); }
    }

    int tg = lane >> 2, t4 = lane & 3;
    if (OUT == 2) {
        // transpose via smem, then coalesced stores
        const int TP = 136;
        bf16* tbuf = (bf16*)smem;
        #pragma unroll
        for (int pass = 0; pass < 2; pass++) {
            #pragma unroll
            for (int mt = 0; mt < 2; mt++)
                #pragma unroll
                for (int rp = 0; rp < 2; rp++) {
                    int ml = wm*32 + mt*16 + tg + rp*8;
                    #pragma unroll
                    for (int nt = 0; nt < 4; nt++) {
                        int cl = wn*32 + nt*8 + t4*2;
                        float c0 = acc[mt][nt][rp*2+0], c1 = acc[mt][nt][rp*2+1];
                        bf16 h0, l0, h1, l1;
                        split(c0, h0, l0); split(c1, h1, l1);
                        tbuf[(cl+0)*TP + ml] = pass ? l0 : h0;
                        tbuf[(cl+1)*TP + ml] = pass ? l1 : h1;
                    }
                }
            __syncthreads();
            {
                int row = tid >> 2, part = tid & 3;        // 128 rows x 4 quarters of 32
                bf16* dst = (pass ? Clo : Chi) + (long long)(bx*128 + row) * ldc + by*128 + part*32;
                const uint4* s4 = (const uint4*)(tbuf + row*TP + part*32);
                uint4* d4 = (uint4*)dst;
                #pragma unroll
                for (int j = 0; j < 4; j++) d4[j] = s4[j];
            }
            __syncthreads();
        }
        return;
    }
    #pragma unroll
    for (int mt = 0; mt < 2; mt++)
        #pragma unroll
        for (int rp = 0; rp < 2; rp++) {
            int m = by*128 + wm*32 + mt*16 + tg + rp*8;
            #pragma unroll
            for (int nt = 0; nt < 4; nt++) {
                int col = bx*128 + wn*32 + nt*8 + t4*2;
                *(float2*)(Cf + (long long)m * ldc + col)
                    = make_float2(acc[mt][nt][rp*2+0], acc[mt][nt][rp*2+1]);
            }
        }
}

// ---------------- fused flash attention, key blocks of 64, cp.async double buffer ----------------
// 1D grid 256 CTAs (big qb first), 256 threads, warp w owns q rows w*16..+15.
#define AQ     0
#define AQLO   34816
#define ABUF   69632
#define OBK_LO 17408         // Klo within buffer
#define OBV_HI 34816         // Vhi within buffer
#define OBV_LO 53248         // Vlo within buffer
#define BUFSZ  71680
#define ASMEM  (ABUF + 2*BUFSZ)

__global__ void __launch_bounds__(256, 1)
attn_kernel(const bf16* __restrict__ qhi, const bf16* __restrict__ qlo,
            const bf16* __restrict__ khi, const bf16* __restrict__ klo,
            const bf16* __restrict__ vthi, const bf16* __restrict__ vtlo,
            const int* __restrict__ mask, const int* __restrict__ mflag,
            bf16* __restrict__ ahi, bf16* __restrict__ alo)
{
    int bid = blockIdx.x;
    int h  = bid & 15;
    int qb = 15 - (bid >> 4);            // big CTAs first (LPT)
    extern __shared__ char smem[];
    uint32_t sb = smem_u32(smem);
    int tid = threadIdx.x, lane = tid & 31, wid = tid >> 5;
    int tg = lane >> 2, t4 = lane & 3;

    // resident Q tiles (hi & lo): 128 rows x 128 cols, stride 272B
    {
        int r = tid >> 1, cb = (tid & 1) * 64;
        const uint4* s0 = (const uint4*)(qhi + (size_t)(qb*128 + r)*HID + h*128 + cb);
        const uint4* s1 = (const uint4*)(qlo + (size_t)(qb*128 + r)*HID + h*128 + cb);
        uint4* d0 = (uint4*)(smem + AQ   + r*272 + cb*2);
        uint4* d1 = (uint4*)(smem + AQLO + r*272 + cb*2);
        #pragma unroll
        for (int j = 0; j < 8; j++) { d0[j] = s0[j]; d1[j] = s1[j]; }
    }

    // async K/V loader: K 64x128 (stride 272), V^T 128x64 (stride 144)
    int rk = tid >> 2, ck = (tid & 3) * 32;
    int rv = tid >> 1, cv = (tid & 1) * 32;
    auto issue = [&](int tb, int buf) {
        uint32_t bp = sb + ABUF + buf * BUFSZ;
        const bf16* sk0 = khi  + (size_t)(tb*64 + rk)*HID + h*128 + ck;
        const bf16* sk1 = klo  + (size_t)(tb*64 + rk)*HID + h*128 + ck;
        uint32_t dk = bp + rk*272 + ck*2;
        #pragma unroll
        for (int j = 0; j < 4; j++) {
            cpa16(dk + j*16,          sk0 + j*8);
            cpa16(dk + OBK_LO + j*16, sk1 + j*8);
        }
        const bf16* sv0 = vthi + (size_t)(h*128 + rv)*SEQ + tb*64 + cv;
        const bf16* sv1 = vtlo + (size_t)(h*128 + rv)*SEQ + tb*64 + cv;
        uint32_t dv = bp + OBV_HI + rv*144 + cv*2;
        #pragma unroll
        for (int j = 0; j < 4; j++) {
            cpa16(dv + j*16,                   sv0 + j*8);
            cpa16(dv + (OBV_LO-OBV_HI) + j*16, sv1 + j*8);
        }
    };

    float o[16][4];
    #pragma unroll
    for (int i = 0; i < 16; i++)
        #pragma unroll
        for (int j = 0; j < 4; j++) o[i][j] = 0.f;
    float m0 = -INFINITY, m1 = -INFINITY, l0 = 0.f, l1 = 0.f;

    uint32_t lrow = (lane & 7) + ((lane >> 3) & 1) * 8;
    uint32_t kcol = ((lane >> 4) & 1) * 16;
    uint32_t arow = sb + AQ + (wid*16 + lrow) * 272 + kcol;
    uint32_t bro272 = lrow * 272 + kcol;
    uint32_t bro144 = lrow * 144 + kcol;
    int rowg0 = qb*128 + wid*16 + tg;     // this thread's rows: rowg0, rowg0+8
    int wrow0 = qb*128 + wid*16;          // warp's min row

    int NTB = 2*qb + 2;
    issue(0, 0); CP_COMMIT();

    for (int tb = 0; tb < NTB; tb++) {
        if (tb + 1 < NTB) issue(tb + 1, (tb + 1) & 1);
        CP_COMMIT();
        CP_WAIT(1);                       // block tb landed
        __syncthreads();

        uint32_t kb = sb + ABUF + (tb & 1) * BUFSZ;

        // ---- S = Q K^T (warp: 16 rows x 64 cols); Q pre-scaled by 1/sqrt(d) ----
        float s[8][4];
        #pragma unroll
        for (int i = 0; i < 8; i++)
            #pragma unroll
            for (int j = 0; j < 4; j++) s[i][j] = 0.f;

        #pragma unroll
        for (int ks = 0; ks < 8; ks++) {
            uint32_t ah[4], al[4];
            ldsm4(ah[0], ah[1], ah[2], ah[3], arow + ks*32);
            ldsm4(al[0], al[1], al[2], al[3], arow + ks*32 + (AQLO - AQ));
            #pragma unroll
            for (int np = 0; np < 4; np++) {
                uint32_t rb = kb + np*16*272 + bro272 + ks*32;
                uint32_t r0, r1, r2, r3;
                ldsm4(r0, r1, r2, r3, rb);
                uint32_t bh0[2] = {r0, r2}, bh1[2] = {r1, r3};
                ldsm4(r0, r1, r2, r3, rb + OBK_LO);
                uint32_t bl0[2] = {r0, r2}, bl1[2] = {r1, r3};
                mma16816(s[2*np],   ah, bh0); mma16816(s[2*np],   ah, bl0); mma16816(s[2*np],   al, bh0);
                mma16816(s[2*np+1], ah, bh1); mma16816(s[2*np+1], ah, bl1); mma16816(s[2*np+1], al, bh1);
            }
        }

        // ---- masking (fast path for fully-visible unmasked blocks), row max ----
        float mx0 = -INFINITY, mx1 = -INFINITY;
        bool full = (tb*64 + 63 <= wrow0) && (__ldg(&mflag[tb]) != 0);   // warp-uniform
        if (full) {
            #pragma unroll
            for (int nt = 0; nt < 8; nt++) {
                mx0 = fmaxf(mx0, fmaxf(s[nt][0], s[nt][1]));
                mx1 = fmaxf(mx1, fmaxf(s[nt][2], s[nt][3]));
            }
        } else {
            #pragma unroll
            for (int nt = 0; nt < 8; nt++) {
                int cl = nt*8 + t4*2;
                int cg = tb*64 + cl;
                int2 mk = __ldg((const int2*)&mask[cg]);
                bool v0 = (mk.x != 0), v1 = (mk.y != 0);
                s[nt][0] = (v0 && cg     <= rowg0    ) ? s[nt][0] : -INFINITY;
                s[nt][1] = (v1 && cg + 1 <= rowg0    ) ? s[nt][1] : -INFINITY;
                s[nt][2] = (v0 && cg     <= rowg0 + 8) ? s[nt][2] : -INFINITY;
                s[nt][3] = (v1 && cg + 1 <= rowg0 + 8) ? s[nt][3] : -INFINITY;
                mx0 = fmaxf(mx0, fmaxf(s[nt][0], s[nt][1]));
                mx1 = fmaxf(mx1, fmaxf(s[nt][2], s[nt][3]));
            }
        }
        mx0 = fmaxf(mx0, __shfl_xor_sync(0xffffffffu, mx0, 1));
        mx0 = fmaxf(mx0, __shfl_xor_sync(0xffffffffu, mx0, 2));
        mx1 = fmaxf(mx1, __shfl_xor_sync(0xffffffffu, mx1, 1));
        mx1 = fmaxf(mx1, __shfl_xor_sync(0xffffffffu, mx1, 2));

        float mn0 = fmaxf(m0, mx0), mn1 = fmaxf(m1, mx1);
        float base0 = (mn0 == -INFINITY) ? 0.f : mn0;
        float base1 = (mn1 == -INFINITY) ? 0.f : mn1;
        float f0 = __expf(m0 - base0);
        float f1 = __expf(m1 - base1);
        m0 = mn0; m1 = mn1;

        float sum0 = 0.f, sum1 = 0.f;
        #pragma unroll
        for (int nt = 0; nt < 8; nt++) {
            s[nt][0] = __expf(s[nt][0] - base0);
            s[nt][1] = __expf(s[nt][1] - base0);
            s[nt][2] = __expf(s[nt][2] - base1);
            s[nt][3] = __expf(s[nt][3] - base1);
            sum0 += s[nt][0] + s[nt][1];
            sum1 += s[nt][2] + s[nt][3];
        }
        sum0 += __shfl_xor_sync(0xffffffffu, sum0, 1);
        sum0 += __shfl_xor_sync(0xffffffffu, sum0, 2);
        sum1 += __shfl_xor_sync(0xffffffffu, sum1, 1);
        sum1 += __shfl_xor_sync(0xffffffffu, sum1, 2);
        l0 = l0 * f0 + sum0;
        l1 = l1 * f1 + sum1;

        #pragma unroll
        for (int dn = 0; dn < 16; dn++) {
            o[dn][0] *= f0; o[dn][1] *= f0;
            o[dn][2] *= f1; o[dn][3] *= f1;
        }

        // ---- O += P V  (P from registers: C fragment == A fragment layout) ----
        #pragma unroll
        for (int ks = 0; ks < 4; ks++) {
            uint32_t aph[4], apl[4];
            {
                bf16 hh[8], ll[8];
                split(s[2*ks][0], hh[0], ll[0]); split(s[2*ks][1], hh[1], ll[1]);
                split(s[2*ks][2], hh[2], ll[2]); split(s[2*ks][3], hh[3], ll[3]);
                split(s[2*ks+1][0], hh[4], ll[4]); split(s[2*ks+1][1], hh[5], ll[5]);
                split(s[2*ks+1][2], hh[6], ll[6]); split(s[2*ks+1][3], hh[7], ll[7]);
                aph[0] = pack2(hh[0], hh[1]); aph[1] = pack2(hh[2], hh[3]);
                aph[2] = pack2(hh[4], hh[5]); aph[3] = pack2(hh[6], hh[7]);
                apl[0] = pack2(ll[0], ll[1]); apl[1] = pack2(ll[2], ll[3]);
                apl[2] = pack2(ll[4], ll[5]); apl[3] = pack2(ll[6], ll[7]);
            }
            #pragma unroll
            for (int np = 0; np < 8; np++) {
                uint32_t rb = kb + OBV_HI + np*16*144 + bro144 + ks*32;
                uint32_t r0, r1, r2, r3;
                ldsm4(r0, r1, r2, r3, rb);
                uint32_t vh0[2] = {r0, r2}, vh1[2] = {r1, r3};
                ldsm4(r0, r1, r2, r3, rb + (OBV_LO - OBV_HI));
                uint32_t vl0[2] = {r0, r2}, vl1[2] = {r1, r3};
                mma16816(o[2*np],   aph, vh0); mma16816(o[2*np],   aph, vl0); mma16816(o[2*np],   apl, vh0);
                mma16816(o[2*np+1], aph, vh1); mma16816(o[2*np+1], aph, vl1); mma16816(o[2*np+1], apl, vh1);
            }
        }
        __syncthreads();   // buffer tb%2 reusable by issue() next iteration
    }

    // ---- epilogue: O /= l, split to ahi/alo [s, h*128+d] ----
    float i0 = 1.f / l0, i1 = 1.f / l1;
    int mrow = qb*128 + wid*16 + tg;
    #pragma unroll
    for (int dn = 0; dn < 16; dn++) {
        int col = h*128 + dn*8 + t4*2;
        bf16 h0, q0, h1, q1;
        split(o[dn][0]*i0, h0, q0); split(o[dn][1]*i0, h1, q1);
        *(uint32_t*)(ahi + (size_t)mrow*HID + col) = pack2(h0, h1);
        *(uint32_t*)(alo + (size_t)mrow*HID + col) = pack2(q0, q1);
        split(o[dn][2]*i1, h0, q0); split(o[dn][3]*i1, h1, q1);
        *(uint32_t*)(ahi + (size_t)(mrow+8)*HID + col) = pack2(h0, h1);
        *(uint32_t*)(alo + (size_t)(mrow+8)*HID + col) = pack2(q0, q1);
    }
}

// ---------------- launch ----------------
extern "C" void kernel_launch(void* const* d_in, const int* in_sizes, int n_in,
                              void* d_out, int out_size) {
    const float* x    = (const float*)d_in[0];
    const int*   mask = (const int*)d_in[1];
    const float* wq   = (const float*)d_in[2];
    const float* wk   = (const float*)d_in[3];
    const float* wv   = (const float*)d_in[4];
    const float* wo   = (const float*)d_in[5];

    bf16 *xhi, *xlo, *whi, *wlo, *qhi, *qlo, *khi, *klo, *vthi, *vtlo, *ahi, *alo;
    float *qf, *kf;
    int* mflag;
    cudaGetSymbolAddress((void**)&xhi,  g_xhi);  cudaGetSymbolAddress((void**)&xlo,  g_xlo);
    cudaGetSymbolAddress((void**)&whi,  g_whi);  cudaGetSymbolAddress((void**)&wlo,  g_wlo);
    cudaGetSymbolAddress((void**)&qf,   g_qf);   cudaGetSymbolAddress((void**)&kf,   g_kf);
    cudaGetSymbolAddress((void**)&qhi,  g_qhi);  cudaGetSymbolAddress((void**)&qlo,  g_qlo);
    cudaGetSymbolAddress((void**)&khi,  g_khi);  cudaGetSymbolAddress((void**)&klo,  g_klo);
    cudaGetSymbolAddress((void**)&vthi, g_vthi); cudaGetSymbolAddress((void**)&vtlo, g_vtlo);
    cudaGetSymbolAddress((void**)&ahi,  g_ahi);  cudaGetSymbolAddress((void**)&alo,  g_alo);
    cudaGetSymbolAddress((void**)&mflag, g_mflag);

    const size_t WSZ = (size_t)HID * HID;

    cudaFuncSetAttribute(gemm_mma<0>, cudaFuncAttributeMaxDynamicSharedMemorySize, SMEM_SZ);
    cudaFuncSetAttribute(gemm_mma<2>, cudaFuncAttributeMaxDynamicSharedMemorySize, SMEM_SZ);
    cudaFuncSetAttribute(attn_kernel, cudaFuncAttributeMaxDynamicSharedMemorySize, ASMEM);

    // 1. quantize weights -> bf16 hi/lo; mask flags; RoPE tables
    quantize_kernel<<<dim3(GROUPS_PER_W / 8, 4), 256>>>(wq, wk, wv, wo);
    maskflag_kernel<<<1, 32>>>(mask);
    rope_table_kernel<<<SEQ * 64 / 256, 256>>>();

    // 2. x -> bf16 hi/lo
    convert_kernel<<<(SEQ * HID / 4) / 256, 256>>>(x, xhi, xlo);

    // 3. projections
    dim3 g16(16, 16, 1);
    gemm_mma<0><<<g16, 512, SMEM_SZ>>>(xhi, xlo, whi,           wlo,           qf, 0, 0,
                                       HID, HID, HID, HID);
    gemm_mma<0><<<g16, 512, SMEM_SZ>>>(xhi, xlo, whi + WSZ,     wlo + WSZ,     kf, 0, 0,
                                       HID, HID, HID, HID);
    gemm_mma<2><<<g16, 512, SMEM_SZ>>>(xhi, xlo, whi + 2 * WSZ, wlo + 2 * WSZ, 0, vthi, vtlo,
                                       HID, HID, HID, SEQ);

    // 4. RoPE -> bf16 hi/lo (Q pre-scaled by 1/sqrt(d)), table-driven
    rope_kernel<<<dim3(SEQ * NHEADS * 64 / 256, 2), 256>>>(qf, kf, qhi, qlo, khi, klo);

    // 5. fused flash attention -> ahi/alo
    attn_kernel<<<256, 256, ASMEM>>>(qhi, qlo, khi, klo, vthi, vtlo, mask, mflag, ahi, alo);

    // 6. out = attn @ Wo^T -> d_out
    gemm_mma<0><<<g16, 512, SMEM_SZ>>>(ahi, alo, whi + 3 * WSZ, wlo + 3 * WSZ,
                                       (float*)d_out, 0, 0, HID, HID, HID, HID);
}